// round 4
// baseline (speedup 1.0000x reference)
#include <cuda_runtime.h>
#include <cuda_bf16.h>
#include <math.h>

// ---------------- problem constants ----------------
#define Bb 2
#define Ll 2048
#define DM 512
#define DI 1024
#define DS 16
#define DR 32
#define Mrows (Bb*Ll)          // 4096
#define NSLICE 8               // split-K slices for GEMM2

// ---------------- scratch (device globals; allocation-free) ----------------
__device__ float g_xz  [2][(size_t)Mrows*2*DI];
__device__ float g_xc  [2][(size_t)Mrows*DI];
__device__ float g_proj[2][(size_t)Mrows*64];
__device__ float g_pp  [2][NSLICE][(size_t)Mrows*64];
__device__ float g_dt  [2][(size_t)Mrows*DI];
__device__ float g_yg  [2][(size_t)Mrows*DI];
__device__ float g_od  [2][(size_t)Mrows*DM];

// ---------------- helpers ----------------
__device__ __forceinline__ float softplusf(float x) {
    return fmaxf(x, 0.f) + log1pf(__expf(-fabsf(x)));
}
__device__ __forceinline__ float siluf(float x) {
    return x / (1.f + __expf(-x));
}
__device__ __forceinline__ unsigned f2tf(float f) {
    unsigned u;
    asm("cvt.rna.tf32.f32 %0, %1;" : "=r"(u) : "f"(f));
    return u;
}
__device__ __forceinline__ void mma_tf32(float c[4], const unsigned a[4], const unsigned b[2]) {
    asm volatile(
        "mma.sync.aligned.m16n8k8.row.col.f32.tf32.tf32.f32 "
        "{%0,%1,%2,%3}, {%4,%5,%6,%7}, {%8,%9}, {%0,%1,%2,%3};\n"
        : "+f"(c[0]), "+f"(c[1]), "+f"(c[2]), "+f"(c[3])
        : "r"(a[0]), "r"(a[1]), "r"(a[2]), "r"(a[3]), "r"(b[0]), "r"(b[1]));
}
__device__ __forceinline__ void ldsm_x4(unsigned r[4], unsigned addr) {
    asm volatile("ldmatrix.sync.aligned.m8n8.x4.shared.b16 {%0,%1,%2,%3}, [%4];"
        : "=r"(r[0]), "=r"(r[1]), "=r"(r[2]), "=r"(r[3]) : "r"(addr));
}

// ---------------- param structs (2 directions) ----------------
struct GemmP {
    const float* A[2];
    const float* W[2];
    float*       C[2];
    const float* bias[2];
};
struct ConvP {
    const float* xz[2];
    float*       xc[2];
    const float* cw[2];
    const float* cb[2];
};
struct ScanP {
    const float* dt[2];
    const float* xc[2];
    const float* proj[2];
    const float* xz[2];
    const float* Alog[2];
    const float* Dsk[2];
    float*       yg[2];
};

// ================= tf32 tensor-core NT GEMM (ldmatrix fragments) =================
// C[M,N] = A[M,K] * W[N,K]^T, fp32 in/out, tf32 mma accumulate fp32.
// Block tile 128x128, BK=16, 256 threads = 8 warps (2x4), warp tile 64x32.
// M % 128 == 0, N % 128 == 0, K % 16 == 0.
// EPI: 0 = plain store, 1 = softplus(v + bias[col]).
template <int EPI>
__global__ __launch_bounds__(256, 2)
void tgemm_nt(GemmP p, int M, int N, int K, int lda, int ldb, int ldc) {
    const int dir = blockIdx.z;
    const float* __restrict__ A = p.A[dir];
    const float* __restrict__ W = p.W[dir];
    float*       __restrict__ C = p.C[dir];
    const float* bias = p.bias[dir];

    const int cm = blockIdx.y * 128;
    const int cn = blockIdx.x * 128;

    __shared__ unsigned As[128][36];   // [m][k], stride 36 -> conflict-free LDSM
    __shared__ unsigned Bs[128][36];   // [n][k]

    const int t    = threadIdx.x;
    const int lane = t & 31;
    const int wid  = t >> 5;
    const int wm   = (wid >> 2) * 64;   // warp m offset (0 or 64)
    const int wn   = (wid & 3) * 32;    // warp n offset (0..96)
    const int l4   = lane >> 2;
    const int lm   = lane & 3;

    float acc[4][4][4];
#pragma unroll
    for (int mi = 0; mi < 4; mi++)
#pragma unroll
        for (int ni = 0; ni < 4; ni++)
#pragma unroll
            for (int r = 0; r < 4; r++) acc[mi][ni][r] = 0.f;

    // ---- ldmatrix per-lane addresses (byte addresses in shared space) ----
    // A x4: matrices {rows 0-7,k0-3},{rows 8-15,k0-3},{rows 0-7,k4-7},{rows 8-15,k4-7}
    //   lane -> row = lane&15, col = (lane>>4)*4
    // B x4 covers ni pair (2j, 2j+1):
    //   lane -> row = (lane&7) + (lane>>4)*8, col = ((lane>>3)&1)*4
    const unsigned sAs = (unsigned)__cvta_generic_to_shared(&As[0][0]);
    const unsigned sBs = (unsigned)__cvta_generic_to_shared(&Bs[0][0]);
    unsigned aAddr[4], bAddr[2];
    {
        int arw = (lane & 15), acl = (lane >> 4) * 4;
#pragma unroll
        for (int mi = 0; mi < 4; mi++)
            aAddr[mi] = sAs + (unsigned)(((wm + mi * 16 + arw) * 36 + acl) * 4);
        int brw = (lane & 7) + ((lane >> 4) * 8), bcl = ((lane >> 3) & 1) * 4;
#pragma unroll
        for (int j = 0; j < 2; j++)
            bAddr[j] = sBs + (unsigned)(((wn + j * 16 + brw) * 36 + bcl) * 4);
    }

    // loaders: thread covers rows arow, arow+64; 4 k-floats at acol
    const int arow = t >> 2;          // 0..63
    const int acol = (t & 3) * 4;     // 0,4,8,12
    const float* Ap = A + (size_t)(cm + arow) * lda + acol;
    const float* Bp = W + (size_t)(cn + arow) * ldb + acol;

    float4 sa0 = *(const float4*)(Ap);
    float4 sa1 = *(const float4*)(Ap + (size_t)64 * lda);
    float4 sb0 = *(const float4*)(Bp);
    float4 sb1 = *(const float4*)(Bp + (size_t)64 * ldb);

    for (int k0 = 0; k0 < K; k0 += 16) {
        // convert + stage to smem
        {
            uint4 u;
            u.x = f2tf(sa0.x); u.y = f2tf(sa0.y); u.z = f2tf(sa0.z); u.w = f2tf(sa0.w);
            *(uint4*)&As[arow][acol] = u;
            u.x = f2tf(sa1.x); u.y = f2tf(sa1.y); u.z = f2tf(sa1.z); u.w = f2tf(sa1.w);
            *(uint4*)&As[arow + 64][acol] = u;
            u.x = f2tf(sb0.x); u.y = f2tf(sb0.y); u.z = f2tf(sb0.z); u.w = f2tf(sb0.w);
            *(uint4*)&Bs[arow][acol] = u;
            u.x = f2tf(sb1.x); u.y = f2tf(sb1.y); u.z = f2tf(sb1.z); u.w = f2tf(sb1.w);
            *(uint4*)&Bs[arow + 64][acol] = u;
        }
        __syncthreads();

        // prefetch next k-block while computing this one
        if (k0 + 16 < K) {
            sa0 = *(const float4*)(Ap + k0 + 16);
            sa1 = *(const float4*)(Ap + (size_t)64 * lda + k0 + 16);
            sb0 = *(const float4*)(Bp + k0 + 16);
            sb1 = *(const float4*)(Bp + (size_t)64 * ldb + k0 + 16);
        }

#pragma unroll
        for (int ks = 0; ks < 2; ks++) {
            const unsigned koff = (unsigned)(ks * 32);   // 8 k-words = 32 bytes
            unsigned af[4][4], bf[4][2];
#pragma unroll
            for (int mi = 0; mi < 4; mi++)
                ldsm_x4(af[mi], aAddr[mi] + koff);
            {
                unsigned r[4];
                ldsm_x4(r, bAddr[0] + koff);
                bf[0][0] = r[0]; bf[0][1] = r[1]; bf[1][0] = r[2]; bf[1][1] = r[3];
                ldsm_x4(r, bAddr[1] + koff);
                bf[2][0] = r[0]; bf[2][1] = r[1]; bf[3][0] = r[2]; bf[3][1] = r[3];
            }
#pragma unroll
            for (int mi = 0; mi < 4; mi++)
#pragma unroll
                for (int ni = 0; ni < 4; ni++)
                    mma_tf32(acc[mi][ni], af[mi], bf[ni]);
        }
        __syncthreads();
    }

    // epilogue: c0,c1 -> (row, col..col+1); c2,c3 -> (row+8, col..col+1)
#pragma unroll
    for (int mi = 0; mi < 4; mi++) {
#pragma unroll
        for (int ni = 0; ni < 4; ni++) {
            int row = cm + wm + mi * 16 + l4;
            int col = cn + wn + ni * 8 + 2 * lm;
            float v0 = acc[mi][ni][0], v1 = acc[mi][ni][1];
            float v2 = acc[mi][ni][2], v3 = acc[mi][ni][3];
            if (EPI == 1) {
                float b0 = bias[col], b1 = bias[col + 1];
                v0 = softplusf(v0 + b0); v1 = softplusf(v1 + b1);
                v2 = softplusf(v2 + b0); v3 = softplusf(v3 + b1);
            }
            *(float2*)(C + (size_t)row * ldc + col)       = make_float2(v0, v1);
            *(float2*)(C + (size_t)(row + 8) * ldc + col) = make_float2(v2, v3);
        }
    }
}

// ================= fp32 SGEMM (kept for GEMM2 split-K, TN=64) =================
template <int TN, int EPI>
__global__ __launch_bounds__(256, 2)
void sgemm_nt(GemmP p, int M, int N, int K, int lda, int ldb, int ldc) {
    const int dir = blockIdx.z;
    const float* __restrict__ A = p.A[dir];
    const float* __restrict__ W = p.W[dir];
    float*       __restrict__ C = p.C[dir];

    const int cm = blockIdx.y * 128;
    int cn;
    if (EPI == 2) {
        cn = 0;
        A += (size_t)blockIdx.x * K;
        W += (size_t)blockIdx.x * K;
        C += (size_t)blockIdx.x * (size_t)M * ldc;
    } else {
        cn = blockIdx.x * TN;
    }

    __shared__ float As[16][128];
    __shared__ float Bs[16][TN];

    constexpr int WN = TN / 16;
    float acc[8][WN];
#pragma unroll
    for (int i = 0; i < 8; i++)
#pragma unroll
        for (int j = 0; j < WN; j++) acc[i][j] = 0.f;

    const int t  = threadIdx.x;
    const int tr = t >> 4;
    const int tc = t & 15;

    const int ar0 = (t * 2)     >> 2, ak0 = ((t * 2)     & 3) * 4;
    const int ar1 = (t * 2 + 1) >> 2, ak1 = ((t * 2 + 1) & 3) * 4;
    const int br0 = (TN == 128) ? ar0 : (t >> 2);
    const int bk0 = (TN == 128) ? ak0 : ((t & 3) * 4);

    const float* Ap0 = A + (size_t)(cm + ar0) * lda + ak0;
    const float* Ap1 = A + (size_t)(cm + ar1) * lda + ak1;
    const float* Bp0 = W + (size_t)(cn + br0) * ldb + bk0;
    const float* Bp1 = (TN == 128) ? (W + (size_t)(cn + ar1) * ldb + ak1) : nullptr;

    float4 sa0 = *(const float4*)Ap0;
    float4 sa1 = *(const float4*)Ap1;
    float4 sb0 = *(const float4*)Bp0;
    float4 sb1 = (TN == 128) ? *(const float4*)Bp1 : make_float4(0, 0, 0, 0);

    for (int k0 = 0; k0 < K; k0 += 16) {
        As[ak0 + 0][ar0] = sa0.x; As[ak0 + 1][ar0] = sa0.y;
        As[ak0 + 2][ar0] = sa0.z; As[ak0 + 3][ar0] = sa0.w;
        As[ak1 + 0][ar1] = sa1.x; As[ak1 + 1][ar1] = sa1.y;
        As[ak1 + 2][ar1] = sa1.z; As[ak1 + 3][ar1] = sa1.w;
        Bs[bk0 + 0][br0] = sb0.x; Bs[bk0 + 1][br0] = sb0.y;
        Bs[bk0 + 2][br0] = sb0.z; Bs[bk0 + 3][br0] = sb0.w;
        if (TN == 128) {
            Bs[ak1 + 0][ar1] = sb1.x; Bs[ak1 + 1][ar1] = sb1.y;
            Bs[ak1 + 2][ar1] = sb1.z; Bs[ak1 + 3][ar1] = sb1.w;
        }
        __syncthreads();

        if (k0 + 16 < K) {
            sa0 = *(const float4*)(Ap0 + k0 + 16);
            sa1 = *(const float4*)(Ap1 + k0 + 16);
            sb0 = *(const float4*)(Bp0 + k0 + 16);
            if (TN == 128) sb1 = *(const float4*)(Bp1 + k0 + 16);
        }

#pragma unroll
        for (int k = 0; k < 16; k++) {
            float a[8], bq[WN];
            *(float4*)&a[0] = *(const float4*)&As[k][tr * 8];
            *(float4*)&a[4] = *(const float4*)&As[k][tr * 8 + 4];
            *(float4*)&bq[0] = *(const float4*)&Bs[k][tc * WN];
            if (TN == 128)
                *(float4*)&bq[4] = *(const float4*)&Bs[k][tc * WN + 4];
#pragma unroll
            for (int i = 0; i < 8; i++)
#pragma unroll
                for (int j = 0; j < WN; j++)
                    acc[i][j] = fmaf(a[i], bq[j], acc[i][j]);
        }
        __syncthreads();
    }

#pragma unroll
    for (int i = 0; i < 8; i++) {
        int row = cm + tr * 8 + i;
        float* Crow = C + (size_t)row * ldc + cn + tc * WN;
        float4 v0 = make_float4(acc[i][0], acc[i][1], acc[i][2], acc[i][3]);
        *(float4*)(Crow) = v0;
        if (TN == 128) {
            float4 v1 = make_float4(acc[i][4], acc[i][5], acc[i][6], acc[i][7]);
            *(float4*)(Crow + 4) = v1;
        }
    }
}

// ---------------- split-K reduction for proj ----------------
__global__ void reduce_proj_kernel(const float* __restrict__ part,
                                   float* __restrict__ proj) {
    int i = blockIdx.x * blockDim.x + threadIdx.x;
    const int per = Mrows * 64;
    if (i >= 2 * per) return;
    int dirn = i / per;
    int off  = i - dirn * per;
    const float* b = part + (size_t)dirn * NSLICE * per + off;
    float s = 0.f;
#pragma unroll
    for (int sidx = 0; sidx < NSLICE; sidx++)
        s += b[(size_t)sidx * per];
    proj[(size_t)dirn * per + off] = s;
}

// ---------------- causal depthwise conv(4) + bias + silu (dir1 reads flipped) ---
__global__ void conv_silu_kernel(ConvP p) {
    const int dir = blockIdx.y;
    const float* __restrict__ xz = p.xz[dir];
    float*       __restrict__ xc = p.xc[dir];
    const float* __restrict__ cw = p.cw[dir];
    const float* __restrict__ cb = p.cb[dir];

    int i = blockIdx.x * blockDim.x + threadIdx.x;
    if (i >= Mrows * DI) return;
    int d  = i & (DI - 1);
    int bl = i >> 10;
    int l  = bl & (Ll - 1);
    int b  = bl >> 11;

    float w0 = cw[d * 4 + 0], w1 = cw[d * 4 + 1], w2 = cw[d * 4 + 2], w3 = cw[d * 4 + 3];
    float s = cb[d];
#pragma unroll
    for (int k = 0; k < 4; k++) {
        int j = l - 3 + k;
        if (j >= 0) {
            int pr = (dir == 0) ? j : (Ll - 1 - j);
            float wv = (k == 0) ? w0 : (k == 1) ? w1 : (k == 2) ? w2 : w3;
            s = fmaf(xz[((size_t)b * Ll + pr) * (2 * DI) + d], wv, s);
        }
    }
    xc[i] = siluf(s);
}

// ---------------- selective scan, software-pipelined ----------------
__global__ void scan_kernel(ScanP p) {
    const int dir = blockIdx.y;
    const float* __restrict__ dt   = p.dt[dir];
    const float* __restrict__ xc   = p.xc[dir];
    const float* __restrict__ proj = p.proj[dir];
    const float* __restrict__ xz   = p.xz[dir];
    const float* __restrict__ Alog = p.Alog[dir];
    const float* __restrict__ Dsk  = p.Dsk[dir];
    float*       __restrict__ yg   = p.yg[dir];

    int tid = blockIdx.x * blockDim.x + threadIdx.x;
    int grp = tid >> 4;
    int n   = tid & 15;
    int b = grp >> 10;
    int d = grp & (DI - 1);

    const float Ad = -__expf(Alog[d * DS + n]);
    const float Dv = Dsk[d];
    float h = 0.f;

    const float* pdt = dt   + ((size_t)b * Ll) * DI + d;
    const float* pxc = xc   + ((size_t)b * Ll) * DI + d;
    const float* pBC = proj + ((size_t)b * Ll) * 64;
    const ptrdiff_t zs = (dir == 0) ? (ptrdiff_t)(2 * DI) : -(ptrdiff_t)(2 * DI);
    const float* pz = (dir == 0)
        ? xz + ((size_t)b * Ll) * (2 * DI) + DI + d
        : xz + ((size_t)b * Ll + (Ll - 1)) * (2 * DI) + DI + d;
    float* pyg = yg + ((size_t)b * Ll) * DI + d;

    float dtv = pdt[0];
    float u   = pxc[0];
    float Bv  = pBC[32 + n];
    float Cv  = pBC[48 + n];
    float zv  = pz[0];

#pragma unroll 2
    for (int l = 0; l < Ll; l++) {
        float ndt = 0.f, nu = 0.f, nB = 0.f, nC = 0.f, nz = 0.f;
        if (l + 1 < Ll) {
            ndt = pdt[(size_t)(l + 1) * DI];
            nu  = pxc[(size_t)(l + 1) * DI];
            nB  = pBC[(size_t)(l + 1) * 64 + 32 + n];
            nC  = pBC[(size_t)(l + 1) * 64 + 48 + n];
            nz  = pz[(ptrdiff_t)(l + 1) * zs];
        }
        float dA = __expf(dtv * Ad);
        h = fmaf(dA, h, dtv * Bv * u);
        float y = h * Cv;
        y += __shfl_xor_sync(0xffffffffu, y, 8);
        y += __shfl_xor_sync(0xffffffffu, y, 4);
        y += __shfl_xor_sync(0xffffffffu, y, 2);
        y += __shfl_xor_sync(0xffffffffu, y, 1);
        if (n == 0)
            pyg[(size_t)l * DI] = (y + u * Dv) * siluf(zv);
        dtv = ndt; u = nu; Bv = nB; Cv = nC; zv = nz;
    }
}

// ---------------- combine fw + flipped bw, LayerNorm, silu + residual ----------
__global__ void combine_kernel(const float* __restrict__ f,
                               const float* __restrict__ bw,
                               const float* __restrict__ x,
                               const float* __restrict__ g,
                               const float* __restrict__ beta,
                               float* __restrict__ out) {
    int row = blockIdx.x;
    int b = row >> 11;
    int l = row & (Ll - 1);
    const float* fr = f  + (size_t)row * DM;
    const float* br = bw + ((size_t)b * Ll + (Ll - 1 - l)) * DM;

    int c0 = threadIdx.x;
    int c1 = threadIdx.x + 256;
    float v0 = 0.5f * (fr[c0] + br[c0]);
    float v1 = 0.5f * (fr[c1] + br[c1]);

    float s1 = v0 + v1;
    float s2 = v0 * v0 + v1 * v1;
#pragma unroll
    for (int o = 16; o; o >>= 1) {
        s1 += __shfl_xor_sync(0xffffffffu, s1, o);
        s2 += __shfl_xor_sync(0xffffffffu, s2, o);
    }
    __shared__ float sh1[8], sh2[8];
    __shared__ float s_mu, s_rstd;
    int w = threadIdx.x >> 5, ln = threadIdx.x & 31;
    if (ln == 0) { sh1[w] = s1; sh2[w] = s2; }
    __syncthreads();
    if (threadIdx.x == 0) {
        float a = 0.f, q = 0.f;
#pragma unroll
        for (int i = 0; i < 8; i++) { a += sh1[i]; q += sh2[i]; }
        float mu  = a * (1.f / DM);
        float var = q * (1.f / DM) - mu * mu;
        s_mu   = mu;
        s_rstd = rsqrtf(var + 1e-5f);
    }
    __syncthreads();
    float mu = s_mu, rstd = s_rstd;
    const float* xr = x + (size_t)row * DM;
    float o0 = (v0 - mu) * rstd * g[c0] + beta[c0];
    float o1 = (v1 - mu) * rstd * g[c1] + beta[c1];
    out[(size_t)row * DM + c0] = siluf(o0) + xr[c0];
    out[(size_t)row * DM + c1] = siluf(o1) + xr[c1];
}

// ---------------- launch ----------------
extern "C" void kernel_launch(void* const* d_in, const int* in_sizes, int n_in,
                              void* d_out, int out_size) {
    const float* x = (const float*)d_in[0];
    const float* fW_in  = (const float*)d_in[1];
    const float* fcw    = (const float*)d_in[2];
    const float* fcb    = (const float*)d_in[3];
    const float* fWxp   = (const float*)d_in[4];
    const float* fWdt   = (const float*)d_in[5];
    const float* fbdt   = (const float*)d_in[6];
    const float* fAlog  = (const float*)d_in[7];
    const float* fDsk   = (const float*)d_in[8];
    const float* fWout  = (const float*)d_in[9];
    const float* bW_in  = (const float*)d_in[10];
    const float* bcw    = (const float*)d_in[11];
    const float* bcb    = (const float*)d_in[12];
    const float* bWxp   = (const float*)d_in[13];
    const float* bWdt   = (const float*)d_in[14];
    const float* bbdt   = (const float*)d_in[15];
    const float* bAlog  = (const float*)d_in[16];
    const float* bDsk   = (const float*)d_in[17];
    const float* bWout  = (const float*)d_in[18];
    const float* ln_g   = (const float*)d_in[19];
    const float* ln_b   = (const float*)d_in[20];
    float* out = (float*)d_out;

    float *xz, *xc, *proj, *pp, *dtb, *ygb, *od;
    cudaGetSymbolAddress((void**)&xz,   g_xz);
    cudaGetSymbolAddress((void**)&xc,   g_xc);
    cudaGetSymbolAddress((void**)&proj, g_proj);
    cudaGetSymbolAddress((void**)&pp,   g_pp);
    cudaGetSymbolAddress((void**)&dtb,  g_dt);
    cudaGetSymbolAddress((void**)&ygb,  g_yg);
    cudaGetSymbolAddress((void**)&od,   g_od);

    const size_t SXZ = (size_t)Mrows * 2 * DI;
    const size_t SXC = (size_t)Mrows * DI;
    const size_t SPJ = (size_t)Mrows * 64;
    const size_t SOD = (size_t)Mrows * DM;

    float* xz0 = xz;   float* xz1 = xz + SXZ;
    float* xc0 = xc;   float* xc1 = xc + SXC;
    float* pj0 = proj; float* pj1 = proj + SPJ;
    float* pp0 = pp;   float* pp1 = pp + (size_t)NSLICE * SPJ;
    float* dt0 = dtb;  float* dt1 = dtb + SXC;
    float* yg0 = ygb;  float* yg1 = ygb + SXC;
    float* od0 = od;   float* od1 = od + SOD;

    // 1. GEMM1 (tf32): xz' = x * W_in^T (both dirs share un-flipped A)
    {
        GemmP p;
        p.A[0] = x;     p.A[1] = x;
        p.W[0] = fW_in; p.W[1] = bW_in;
        p.C[0] = xz0;   p.C[1] = xz1;
        p.bias[0] = nullptr; p.bias[1] = nullptr;
        dim3 grid(2 * DI / 128, Mrows / 128, 2);
        tgemm_nt<0><<<grid, 256>>>(p, Mrows, 2 * DI, DM, DM, DM, 2 * DI);
    }

    // 2. conv + silu (dir1 reads flipped rows; xc1 comes out in bw order)
    {
        ConvP p;
        p.xz[0] = xz0; p.xz[1] = xz1;
        p.xc[0] = xc0; p.xc[1] = xc1;
        p.cw[0] = fcw; p.cw[1] = bcw;
        p.cb[0] = fcb; p.cb[1] = bcb;
        dim3 grid((Mrows * DI + 255) / 256, 2);
        conv_silu_kernel<<<grid, 256>>>(p);
    }

    // 3. GEMM2 split-K (fp32): partial = xc * Wxp^T over K slices of 128
    {
        GemmP p;
        p.A[0] = xc0;  p.A[1] = xc1;
        p.W[0] = fWxp; p.W[1] = bWxp;
        p.C[0] = pp0;  p.C[1] = pp1;
        p.bias[0] = nullptr; p.bias[1] = nullptr;
        dim3 grid(NSLICE, Mrows / 128, 2);
        sgemm_nt<64, 2><<<grid, 256>>>(p, Mrows, 64, DI / NSLICE, DI, DI, 64);
    }

    // 4. reduce split-K partials
    reduce_proj_kernel<<<(2 * Mrows * 64 + 255) / 256, 256>>>(pp, proj);

    // 5. GEMM3 (tf32): dt = softplus(dtpart * Wdt^T + b_dt)
    {
        GemmP p;
        p.A[0] = pj0;  p.A[1] = pj1;
        p.W[0] = fWdt; p.W[1] = bWdt;
        p.C[0] = dt0;  p.C[1] = dt1;
        p.bias[0] = fbdt; p.bias[1] = bbdt;
        dim3 grid(DI / 128, Mrows / 128, 2);
        tgemm_nt<1><<<grid, 256>>>(p, Mrows, DI, DR, 64, DR, DI);
    }

    // 6. scan (+ D skip + z gate; dir1 reads z from flipped rows)
    {
        ScanP p;
        p.dt[0] = dt0;   p.dt[1] = dt1;
        p.xc[0] = xc0;   p.xc[1] = xc1;
        p.proj[0] = pj0; p.proj[1] = pj1;
        p.xz[0] = xz0;   p.xz[1] = xz1;
        p.Alog[0] = fAlog; p.Alog[1] = bAlog;
        p.Dsk[0] = fDsk;   p.Dsk[1] = bDsk;
        p.yg[0] = yg0;   p.yg[1] = yg1;
        dim3 grid((Bb * DI * DS) / 256, 2);
        scan_kernel<<<grid, 256>>>(p);
    }

    // 7. GEMM4 (tf32): od = yg * Wout^T
    {
        GemmP p;
        p.A[0] = yg0;   p.A[1] = yg1;
        p.W[0] = fWout; p.W[1] = bWout;
        p.C[0] = od0;   p.C[1] = od1;
        p.bias[0] = nullptr; p.bias[1] = nullptr;
        dim3 grid(DM / 128, Mrows / 128, 2);
        tgemm_nt<0><<<grid, 256>>>(p, Mrows, DM, DI, DI, DI, DM);
    }

    // 8. combine + LN + silu + residual (flips od1 back)
    combine_kernel<<<Mrows, 256>>>(od0, od1, x, ln_g, ln_b, out);
}

// round 5
// speedup vs baseline: 1.0030x; 1.0030x over previous
#include <cuda_runtime.h>
#include <cuda_bf16.h>
#include <math.h>

// ---------------- problem constants ----------------
#define Bb 2
#define Ll 2048
#define DM 512
#define DI 1024
#define DS 16
#define DR 32
#define Mrows (Bb*Ll)          // 4096
#define NSLICE 8               // split-K slices for GEMM2

// ---------------- scratch (device globals; allocation-free) ----------------
__device__ float g_xz  [2][(size_t)Mrows*2*DI];
__device__ float g_xc  [2][(size_t)Mrows*DI];
__device__ float g_proj[2][(size_t)Mrows*64];
__device__ float g_pp  [2][NSLICE][(size_t)Mrows*64];
__device__ float g_dt  [2][(size_t)Mrows*DI];
__device__ float g_yg  [2][(size_t)Mrows*DI];
__device__ float g_od  [2][(size_t)Mrows*DM];

// ---------------- helpers ----------------
__device__ __forceinline__ float softplusf(float x) {
    return fmaxf(x, 0.f) + log1pf(__expf(-fabsf(x)));
}
__device__ __forceinline__ float siluf(float x) {
    return x / (1.f + __expf(-x));
}
__device__ __forceinline__ unsigned f2tf(float f) {
    unsigned u;
    asm("cvt.rna.tf32.f32 %0, %1;" : "=r"(u) : "f"(f));
    return u;
}
__device__ __forceinline__ void mma_tf32(float c[4], const unsigned a[4], const unsigned b[2]) {
    asm volatile(
        "mma.sync.aligned.m16n8k8.row.col.f32.tf32.tf32.f32 "
        "{%0,%1,%2,%3}, {%4,%5,%6,%7}, {%8,%9}, {%0,%1,%2,%3};\n"
        : "+f"(c[0]), "+f"(c[1]), "+f"(c[2]), "+f"(c[3])
        : "r"(a[0]), "r"(a[1]), "r"(a[2]), "r"(a[3]), "r"(b[0]), "r"(b[1]));
}
__device__ __forceinline__ void ldsm_x4(unsigned r[4], unsigned addr) {
    asm volatile("ldmatrix.sync.aligned.m8n8.x4.shared.b16 {%0,%1,%2,%3}, [%4];"
        : "=r"(r[0]), "=r"(r[1]), "=r"(r[2]), "=r"(r[3]) : "r"(addr));
}

// ---------------- param structs (2 directions) ----------------
struct GemmP {
    const float* A[2];
    const float* W[2];
    float*       C[2];
    const float* bias[2];
};
struct ConvP {
    const float* xz[2];
    float*       xc[2];
    const float* cw[2];
    const float* cb[2];
};
struct ScanP {
    const float* dt[2];
    const float* xc[2];
    const float* proj[2];
    const float* xz[2];
    const float* Alog[2];
    const float* Dsk[2];
    float*       yg[2];
};

// profiling-slot shifter (slot lands on 4th program launch)
__global__ void dummy_kernel() {}

// ================= tf32 tensor-core NT GEMM, ping-pong double buffer ==========
// C[M,N] = A[M,K] * W[N,K]^T, fp32 in/out, tf32 mma accumulate fp32.
// Block tile 128x128, BK=16, 256 threads = 8 warps (2x4), warp tile 64x32.
// Dynamic smem: 2 buffers x (A 128x36 + B 128x36) words = 73728 bytes.
// EPI: 0 = plain store, 1 = softplus(v + bias[col]).
#define TG_BUF_WORDS (128*36*2)          // 9216 words per buffer (A then B)
#define TG_SMEM_BYTES (2*TG_BUF_WORDS*4) // 73728
template <int EPI>
__global__ __launch_bounds__(256, 2)
void tgemm_nt(GemmP p, int M, int N, int K, int lda, int ldb, int ldc) {
    extern __shared__ unsigned sm[];
    const int dir = blockIdx.z;
    const float* __restrict__ A = p.A[dir];
    const float* __restrict__ W = p.W[dir];
    float*       __restrict__ C = p.C[dir];
    const float* bias = p.bias[dir];

    const int cm = blockIdx.y * 128;
    const int cn = blockIdx.x * 128;

    const int t    = threadIdx.x;
    const int lane = t & 31;
    const int wid  = t >> 5;
    const int wm   = (wid >> 2) * 64;   // warp m offset (0 or 64)
    const int wn   = (wid & 3) * 32;    // warp n offset (0..96)
    const int l4   = lane >> 2;
    const int lm   = lane & 3;

    float acc[4][4][4];
#pragma unroll
    for (int mi = 0; mi < 4; mi++)
#pragma unroll
        for (int ni = 0; ni < 4; ni++)
#pragma unroll
            for (int r = 0; r < 4; r++) acc[mi][ni][r] = 0.f;

    // ---- ldmatrix per-lane byte addresses within buffer 0 ----
    const unsigned sBase = (unsigned)__cvta_generic_to_shared(sm);
    unsigned aAddr[4], bAddr[2];
    {
        int arw = (lane & 15), acl = (lane >> 4) * 4;
#pragma unroll
        for (int mi = 0; mi < 4; mi++)
            aAddr[mi] = sBase + (unsigned)(((wm + mi * 16 + arw) * 36 + acl) * 4);
        int brw = (lane & 7) + ((lane >> 4) * 8), bcl = ((lane >> 3) & 1) * 4;
#pragma unroll
        for (int j = 0; j < 2; j++)
            bAddr[j] = sBase + (unsigned)((4608 + (wn + j * 16 + brw) * 36 + bcl) * 4);
    }

    // loaders: thread covers rows arow, arow+64; 4 k-floats at acol
    const int arow = t >> 2;          // 0..63
    const int acol = (t & 3) * 4;     // 0,4,8,12
    const float* Ap = A + (size_t)(cm + arow) * lda + acol;
    const float* Bp = W + (size_t)(cn + arow) * ldb + acol;
    const int sidx = arow * 36 + acol;

    // prologue: load + stage buffer 0
    {
        float4 a0 = *(const float4*)(Ap);
        float4 a1 = *(const float4*)(Ap + (size_t)64 * lda);
        float4 b0 = *(const float4*)(Bp);
        float4 b1 = *(const float4*)(Bp + (size_t)64 * ldb);
        uint4 u;
        u.x = f2tf(a0.x); u.y = f2tf(a0.y); u.z = f2tf(a0.z); u.w = f2tf(a0.w);
        *(uint4*)&sm[sidx] = u;
        u.x = f2tf(a1.x); u.y = f2tf(a1.y); u.z = f2tf(a1.z); u.w = f2tf(a1.w);
        *(uint4*)&sm[sidx + 64 * 36] = u;
        u.x = f2tf(b0.x); u.y = f2tf(b0.y); u.z = f2tf(b0.z); u.w = f2tf(b0.w);
        *(uint4*)&sm[4608 + sidx] = u;
        u.x = f2tf(b1.x); u.y = f2tf(b1.y); u.z = f2tf(b1.z); u.w = f2tf(b1.w);
        *(uint4*)&sm[4608 + sidx + 64 * 36] = u;
    }
    __syncthreads();

    int cur = 0;
    for (int k0 = 0; k0 < K; k0 += 16) {
        const bool more = (k0 + 16) < K;
        float4 na0, na1, nb0, nb1;
        if (more) {
            na0 = *(const float4*)(Ap + k0 + 16);
            na1 = *(const float4*)(Ap + (size_t)64 * lda + k0 + 16);
            nb0 = *(const float4*)(Bp + k0 + 16);
            nb1 = *(const float4*)(Bp + (size_t)64 * ldb + k0 + 16);
        }

        // compute from buffer `cur`
        const unsigned boff = (unsigned)(cur * TG_BUF_WORDS * 4);
#pragma unroll
        for (int ks = 0; ks < 2; ks++) {
            const unsigned koff = boff + (unsigned)(ks * 32);
            unsigned af[4][4], bf[4][2];
#pragma unroll
            for (int mi = 0; mi < 4; mi++)
                ldsm_x4(af[mi], aAddr[mi] + koff);
            {
                unsigned r[4];
                ldsm_x4(r, bAddr[0] + koff);
                bf[0][0] = r[0]; bf[0][1] = r[1]; bf[1][0] = r[2]; bf[1][1] = r[3];
                ldsm_x4(r, bAddr[1] + koff);
                bf[2][0] = r[0]; bf[2][1] = r[1]; bf[3][0] = r[2]; bf[3][1] = r[3];
            }
#pragma unroll
            for (int mi = 0; mi < 4; mi++)
#pragma unroll
                for (int ni = 0; ni < 4; ni++)
                    mma_tf32(acc[mi][ni], af[mi], bf[ni]);
        }

        // stage next tile into the other buffer (overlaps with other warps' mma)
        if (more) {
            unsigned* dst = sm + (1 - cur) * TG_BUF_WORDS;
            uint4 u;
            u.x = f2tf(na0.x); u.y = f2tf(na0.y); u.z = f2tf(na0.z); u.w = f2tf(na0.w);
            *(uint4*)&dst[sidx] = u;
            u.x = f2tf(na1.x); u.y = f2tf(na1.y); u.z = f2tf(na1.z); u.w = f2tf(na1.w);
            *(uint4*)&dst[sidx + 64 * 36] = u;
            u.x = f2tf(nb0.x); u.y = f2tf(nb0.y); u.z = f2tf(nb0.z); u.w = f2tf(nb0.w);
            *(uint4*)&dst[4608 + sidx] = u;
            u.x = f2tf(nb1.x); u.y = f2tf(nb1.y); u.z = f2tf(nb1.z); u.w = f2tf(nb1.w);
            *(uint4*)&dst[4608 + sidx + 64 * 36] = u;
        }
        __syncthreads();
        cur ^= 1;
    }

    // epilogue
#pragma unroll
    for (int mi = 0; mi < 4; mi++) {
#pragma unroll
        for (int ni = 0; ni < 4; ni++) {
            int row = cm + wm + mi * 16 + l4;
            int col = cn + wn + ni * 8 + 2 * lm;
            float v0 = acc[mi][ni][0], v1 = acc[mi][ni][1];
            float v2 = acc[mi][ni][2], v3 = acc[mi][ni][3];
            if (EPI == 1) {
                float b0 = bias[col], b1 = bias[col + 1];
                v0 = softplusf(v0 + b0); v1 = softplusf(v1 + b1);
                v2 = softplusf(v2 + b0); v3 = softplusf(v3 + b1);
            }
            *(float2*)(C + (size_t)row * ldc + col)       = make_float2(v0, v1);
            *(float2*)(C + (size_t)(row + 8) * ldc + col) = make_float2(v2, v3);
        }
    }
}

// ================= fp32 SGEMM (kept for GEMM2 split-K, TN=64) =================
template <int TN, int EPI>
__global__ __launch_bounds__(256, 2)
void sgemm_nt(GemmP p, int M, int N, int K, int lda, int ldb, int ldc) {
    const int dir = blockIdx.z;
    const float* __restrict__ A = p.A[dir];
    const float* __restrict__ W = p.W[dir];
    float*       __restrict__ C = p.C[dir];

    const int cm = blockIdx.y * 128;
    int cn;
    if (EPI == 2) {
        cn = 0;
        A += (size_t)blockIdx.x * K;
        W += (size_t)blockIdx.x * K;
        C += (size_t)blockIdx.x * (size_t)M * ldc;
    } else {
        cn = blockIdx.x * TN;
    }

    __shared__ float As[16][128];
    __shared__ float Bs[16][TN];

    constexpr int WN = TN / 16;
    float acc[8][WN];
#pragma unroll
    for (int i = 0; i < 8; i++)
#pragma unroll
        for (int j = 0; j < WN; j++) acc[i][j] = 0.f;

    const int t  = threadIdx.x;
    const int tr = t >> 4;
    const int tc = t & 15;

    const int ar0 = (t * 2)     >> 2, ak0 = ((t * 2)     & 3) * 4;
    const int ar1 = (t * 2 + 1) >> 2, ak1 = ((t * 2 + 1) & 3) * 4;
    const int br0 = (TN == 128) ? ar0 : (t >> 2);
    const int bk0 = (TN == 128) ? ak0 : ((t & 3) * 4);

    const float* Ap0 = A + (size_t)(cm + ar0) * lda + ak0;
    const float* Ap1 = A + (size_t)(cm + ar1) * lda + ak1;
    const float* Bp0 = W + (size_t)(cn + br0) * ldb + bk0;
    const float* Bp1 = (TN == 128) ? (W + (size_t)(cn + ar1) * ldb + ak1) : nullptr;

    float4 sa0 = *(const float4*)Ap0;
    float4 sa1 = *(const float4*)Ap1;
    float4 sb0 = *(const float4*)Bp0;
    float4 sb1 = (TN == 128) ? *(const float4*)Bp1 : make_float4(0, 0, 0, 0);

    for (int k0 = 0; k0 < K; k0 += 16) {
        As[ak0 + 0][ar0] = sa0.x; As[ak0 + 1][ar0] = sa0.y;
        As[ak0 + 2][ar0] = sa0.z; As[ak0 + 3][ar0] = sa0.w;
        As[ak1 + 0][ar1] = sa1.x; As[ak1 + 1][ar1] = sa1.y;
        As[ak1 + 2][ar1] = sa1.z; As[ak1 + 3][ar1] = sa1.w;
        Bs[bk0 + 0][br0] = sb0.x; Bs[bk0 + 1][br0] = sb0.y;
        Bs[bk0 + 2][br0] = sb0.z; Bs[bk0 + 3][br0] = sb0.w;
        if (TN == 128) {
            Bs[ak1 + 0][ar1] = sb1.x; Bs[ak1 + 1][ar1] = sb1.y;
            Bs[ak1 + 2][ar1] = sb1.z; Bs[ak1 + 3][ar1] = sb1.w;
        }
        __syncthreads();

        if (k0 + 16 < K) {
            sa0 = *(const float4*)(Ap0 + k0 + 16);
            sa1 = *(const float4*)(Ap1 + k0 + 16);
            sb0 = *(const float4*)(Bp0 + k0 + 16);
            if (TN == 128) sb1 = *(const float4*)(Bp1 + k0 + 16);
        }

#pragma unroll
        for (int k = 0; k < 16; k++) {
            float a[8], bq[WN];
            *(float4*)&a[0] = *(const float4*)&As[k][tr * 8];
            *(float4*)&a[4] = *(const float4*)&As[k][tr * 8 + 4];
            *(float4*)&bq[0] = *(const float4*)&Bs[k][tc * WN];
            if (TN == 128)
                *(float4*)&bq[4] = *(const float4*)&Bs[k][tc * WN + 4];
#pragma unroll
            for (int i = 0; i < 8; i++)
#pragma unroll
                for (int j = 0; j < WN; j++)
                    acc[i][j] = fmaf(a[i], bq[j], acc[i][j]);
        }
        __syncthreads();
    }

#pragma unroll
    for (int i = 0; i < 8; i++) {
        int row = cm + tr * 8 + i;
        float* Crow = C + (size_t)row * ldc + cn + tc * WN;
        float4 v0 = make_float4(acc[i][0], acc[i][1], acc[i][2], acc[i][3]);
        *(float4*)(Crow) = v0;
        if (TN == 128) {
            float4 v1 = make_float4(acc[i][4], acc[i][5], acc[i][6], acc[i][7]);
            *(float4*)(Crow + 4) = v1;
        }
    }
}

// ---------------- split-K reduction for proj ----------------
__global__ void reduce_proj_kernel(const float* __restrict__ part,
                                   float* __restrict__ proj) {
    int i = blockIdx.x * blockDim.x + threadIdx.x;
    const int per = Mrows * 64;
    if (i >= 2 * per) return;
    int dirn = i / per;
    int off  = i - dirn * per;
    const float* b = part + (size_t)dirn * NSLICE * per + off;
    float s = 0.f;
#pragma unroll
    for (int sidx = 0; sidx < NSLICE; sidx++)
        s += b[(size_t)sidx * per];
    proj[(size_t)dirn * per + off] = s;
}

// ---------------- causal depthwise conv(4) + bias + silu (dir1 reads flipped) ---
__global__ void conv_silu_kernel(ConvP p) {
    const int dir = blockIdx.y;
    const float* __restrict__ xz = p.xz[dir];
    float*       __restrict__ xc = p.xc[dir];
    const float* __restrict__ cw = p.cw[dir];
    const float* __restrict__ cb = p.cb[dir];

    int i = blockIdx.x * blockDim.x + threadIdx.x;
    if (i >= Mrows * DI) return;
    int d  = i & (DI - 1);
    int bl = i >> 10;
    int l  = bl & (Ll - 1);
    int b  = bl >> 11;

    float w0 = cw[d * 4 + 0], w1 = cw[d * 4 + 1], w2 = cw[d * 4 + 2], w3 = cw[d * 4 + 3];
    float s = cb[d];
#pragma unroll
    for (int k = 0; k < 4; k++) {
        int j = l - 3 + k;
        if (j >= 0) {
            int pr = (dir == 0) ? j : (Ll - 1 - j);
            float wv = (k == 0) ? w0 : (k == 1) ? w1 : (k == 2) ? w2 : w3;
            s = fmaf(xz[((size_t)b * Ll + pr) * (2 * DI) + d], wv, s);
        }
    }
    xc[i] = siluf(s);
}

// ---------------- selective scan, software-pipelined ----------------
__global__ void scan_kernel(ScanP p) {
    const int dir = blockIdx.y;
    const float* __restrict__ dt   = p.dt[dir];
    const float* __restrict__ xc   = p.xc[dir];
    const float* __restrict__ proj = p.proj[dir];
    const float* __restrict__ xz   = p.xz[dir];
    const float* __restrict__ Alog = p.Alog[dir];
    const float* __restrict__ Dsk  = p.Dsk[dir];
    float*       __restrict__ yg   = p.yg[dir];

    int tid = blockIdx.x * blockDim.x + threadIdx.x;
    int grp = tid >> 4;
    int n   = tid & 15;
    int b = grp >> 10;
    int d = grp & (DI - 1);

    const float Ad = -__expf(Alog[d * DS + n]);
    const float Dv = Dsk[d];
    float h = 0.f;

    const float* pdt = dt   + ((size_t)b * Ll) * DI + d;
    const float* pxc = xc   + ((size_t)b * Ll) * DI + d;
    const float* pBC = proj + ((size_t)b * Ll) * 64;
    const ptrdiff_t zs = (dir == 0) ? (ptrdiff_t)(2 * DI) : -(ptrdiff_t)(2 * DI);
    const float* pz = (dir == 0)
        ? xz + ((size_t)b * Ll) * (2 * DI) + DI + d
        : xz + ((size_t)b * Ll + (Ll - 1)) * (2 * DI) + DI + d;
    float* pyg = yg + ((size_t)b * Ll) * DI + d;

    float dtv = pdt[0];
    float u   = pxc[0];
    float Bv  = pBC[32 + n];
    float Cv  = pBC[48 + n];
    float zv  = pz[0];

#pragma unroll 2
    for (int l = 0; l < Ll; l++) {
        float ndt = 0.f, nu = 0.f, nB = 0.f, nC = 0.f, nz = 0.f;
        if (l + 1 < Ll) {
            ndt = pdt[(size_t)(l + 1) * DI];
            nu  = pxc[(size_t)(l + 1) * DI];
            nB  = pBC[(size_t)(l + 1) * 64 + 32 + n];
            nC  = pBC[(size_t)(l + 1) * 64 + 48 + n];
            nz  = pz[(ptrdiff_t)(l + 1) * zs];
        }
        float dA = __expf(dtv * Ad);
        h = fmaf(dA, h, dtv * Bv * u);
        float y = h * Cv;
        y += __shfl_xor_sync(0xffffffffu, y, 8);
        y += __shfl_xor_sync(0xffffffffu, y, 4);
        y += __shfl_xor_sync(0xffffffffu, y, 2);
        y += __shfl_xor_sync(0xffffffffu, y, 1);
        if (n == 0)
            pyg[(size_t)l * DI] = (y + u * Dv) * siluf(zv);
        dtv = ndt; u = nu; Bv = nB; Cv = nC; zv = nz;
    }
}

// ---------------- combine fw + flipped bw, LayerNorm, silu + residual ----------
__global__ void combine_kernel(const float* __restrict__ f,
                               const float* __restrict__ bw,
                               const float* __restrict__ x,
                               const float* __restrict__ g,
                               const float* __restrict__ beta,
                               float* __restrict__ out) {
    int row = blockIdx.x;
    int b = row >> 11;
    int l = row & (Ll - 1);
    const float* fr = f  + (size_t)row * DM;
    const float* br = bw + ((size_t)b * Ll + (Ll - 1 - l)) * DM;

    int c0 = threadIdx.x;
    int c1 = threadIdx.x + 256;
    float v0 = 0.5f * (fr[c0] + br[c0]);
    float v1 = 0.5f * (fr[c1] + br[c1]);

    float s1 = v0 + v1;
    float s2 = v0 * v0 + v1 * v1;
#pragma unroll
    for (int o = 16; o; o >>= 1) {
        s1 += __shfl_xor_sync(0xffffffffu, s1, o);
        s2 += __shfl_xor_sync(0xffffffffu, s2, o);
    }
    __shared__ float sh1[8], sh2[8];
    __shared__ float s_mu, s_rstd;
    int w = threadIdx.x >> 5, ln = threadIdx.x & 31;
    if (ln == 0) { sh1[w] = s1; sh2[w] = s2; }
    __syncthreads();
    if (threadIdx.x == 0) {
        float a = 0.f, q = 0.f;
#pragma unroll
        for (int i = 0; i < 8; i++) { a += sh1[i]; q += sh2[i]; }
        float mu  = a * (1.f / DM);
        float var = q * (1.f / DM) - mu * mu;
        s_mu   = mu;
        s_rstd = rsqrtf(var + 1e-5f);
    }
    __syncthreads();
    float mu = s_mu, rstd = s_rstd;
    const float* xr = x + (size_t)row * DM;
    float o0 = (v0 - mu) * rstd * g[c0] + beta[c0];
    float o1 = (v1 - mu) * rstd * g[c1] + beta[c1];
    out[(size_t)row * DM + c0] = siluf(o0) + xr[c0];
    out[(size_t)row * DM + c1] = siluf(o1) + xr[c1];
}

// ---------------- launch ----------------
extern "C" void kernel_launch(void* const* d_in, const int* in_sizes, int n_in,
                              void* d_out, int out_size) {
    const float* x = (const float*)d_in[0];
    const float* fW_in  = (const float*)d_in[1];
    const float* fcw    = (const float*)d_in[2];
    const float* fcb    = (const float*)d_in[3];
    const float* fWxp   = (const float*)d_in[4];
    const float* fWdt   = (const float*)d_in[5];
    const float* fbdt   = (const float*)d_in[6];
    const float* fAlog  = (const float*)d_in[7];
    const float* fDsk   = (const float*)d_in[8];
    const float* fWout  = (const float*)d_in[9];
    const float* bW_in  = (const float*)d_in[10];
    const float* bcw    = (const float*)d_in[11];
    const float* bcb    = (const float*)d_in[12];
    const float* bWxp   = (const float*)d_in[13];
    const float* bWdt   = (const float*)d_in[14];
    const float* bbdt   = (const float*)d_in[15];
    const float* bAlog  = (const float*)d_in[16];
    const float* bDsk   = (const float*)d_in[17];
    const float* bWout  = (const float*)d_in[18];
    const float* ln_g   = (const float*)d_in[19];
    const float* ln_b   = (const float*)d_in[20];
    float* out = (float*)d_out;

    float *xz, *xc, *proj, *pp, *dtb, *ygb, *od;
    cudaGetSymbolAddress((void**)&xz,   g_xz);
    cudaGetSymbolAddress((void**)&xc,   g_xc);
    cudaGetSymbolAddress((void**)&proj, g_proj);
    cudaGetSymbolAddress((void**)&pp,   g_pp);
    cudaGetSymbolAddress((void**)&dtb,  g_dt);
    cudaGetSymbolAddress((void**)&ygb,  g_yg);
    cudaGetSymbolAddress((void**)&od,   g_od);

    const size_t SXZ = (size_t)Mrows * 2 * DI;
    const size_t SXC = (size_t)Mrows * DI;
    const size_t SPJ = (size_t)Mrows * 64;
    const size_t SOD = (size_t)Mrows * DM;

    float* xz0 = xz;   float* xz1 = xz + SXZ;
    float* xc0 = xc;   float* xc1 = xc + SXC;
    float* pj0 = proj; float* pj1 = proj + SPJ;
    float* pp0 = pp;   float* pp1 = pp + (size_t)NSLICE * SPJ;
    float* dt0 = dtb;  float* dt1 = dtb + SXC;
    float* yg0 = ygb;  float* yg1 = ygb + SXC;
    float* od0 = od;   float* od1 = od + SOD;

    // enable large dynamic smem for the tf32 gemms (idempotent)
    cudaFuncSetAttribute(tgemm_nt<0>, cudaFuncAttributeMaxDynamicSharedMemorySize, TG_SMEM_BYTES);
    cudaFuncSetAttribute(tgemm_nt<1>, cudaFuncAttributeMaxDynamicSharedMemorySize, TG_SMEM_BYTES);

    // 0a-0c: shift the ncu capture slot onto tgemm1 (4th launch)
    dummy_kernel<<<1, 32>>>();
    dummy_kernel<<<1, 32>>>();
    dummy_kernel<<<1, 32>>>();

    // 1. GEMM1 (tf32): xz' = x * W_in^T (both dirs share un-flipped A)
    {
        GemmP p;
        p.A[0] = x;     p.A[1] = x;
        p.W[0] = fW_in; p.W[1] = bW_in;
        p.C[0] = xz0;   p.C[1] = xz1;
        p.bias[0] = nullptr; p.bias[1] = nullptr;
        dim3 grid(2 * DI / 128, Mrows / 128, 2);
        tgemm_nt<0><<<grid, 256, TG_SMEM_BYTES>>>(p, Mrows, 2 * DI, DM, DM, DM, 2 * DI);
    }

    // 2. conv + silu (dir1 reads flipped rows; xc1 comes out in bw order)
    {
        ConvP p;
        p.xz[0] = xz0; p.xz[1] = xz1;
        p.xc[0] = xc0; p.xc[1] = xc1;
        p.cw[0] = fcw; p.cw[1] = bcw;
        p.cb[0] = fcb; p.cb[1] = bcb;
        dim3 grid((Mrows * DI + 255) / 256, 2);
        conv_silu_kernel<<<grid, 256>>>(p);
    }

    // 3. GEMM2 split-K (fp32): partial = xc * Wxp^T over K slices of 128
    {
        GemmP p;
        p.A[0] = xc0;  p.A[1] = xc1;
        p.W[0] = fWxp; p.W[1] = bWxp;
        p.C[0] = pp0;  p.C[1] = pp1;
        p.bias[0] = nullptr; p.bias[1] = nullptr;
        dim3 grid(NSLICE, Mrows / 128, 2);
        sgemm_nt<64, 2><<<grid, 256>>>(p, Mrows, 64, DI / NSLICE, DI, DI, 64);
    }

    // 4. reduce split-K partials
    reduce_proj_kernel<<<(2 * Mrows * 64 + 255) / 256, 256>>>(pp, proj);

    // 5. GEMM3 (tf32): dt = softplus(dtpart * Wdt^T + b_dt)
    {
        GemmP p;
        p.A[0] = pj0;  p.A[1] = pj1;
        p.W[0] = fWdt; p.W[1] = bWdt;
        p.C[0] = dt0;  p.C[1] = dt1;
        p.bias[0] = fbdt; p.bias[1] = bbdt;
        dim3 grid(DI / 128, Mrows / 128, 2);
        tgemm_nt<1><<<grid, 256, TG_SMEM_BYTES>>>(p, Mrows, DI, DR, 64, DR, DI);
    }

    // 6. scan (+ D skip + z gate; dir1 reads z from flipped rows)
    {
        ScanP p;
        p.dt[0] = dt0;   p.dt[1] = dt1;
        p.xc[0] = xc0;   p.xc[1] = xc1;
        p.proj[0] = pj0; p.proj[1] = pj1;
        p.xz[0] = xz0;   p.xz[1] = xz1;
        p.Alog[0] = fAlog; p.Alog[1] = bAlog;
        p.Dsk[0] = fDsk;   p.Dsk[1] = bDsk;
        p.yg[0] = yg0;   p.yg[1] = yg1;
        dim3 grid((Bb * DI * DS) / 256, 2);
        scan_kernel<<<grid, 256>>>(p);
    }

    // 7. GEMM4 (tf32): od = yg * Wout^T
    {
        GemmP p;
        p.A[0] = yg0;   p.A[1] = yg1;
        p.W[0] = fWout; p.W[1] = bWout;
        p.C[0] = od0;   p.C[1] = od1;
        p.bias[0] = nullptr; p.bias[1] = nullptr;
        dim3 grid(DM / 128, Mrows / 128, 2);
        tgemm_nt<0><<<grid, 256, TG_SMEM_BYTES>>>(p, Mrows, DM, DI, DI, DI, DM);
    }

    // 8. combine + LN + silu + residual (flips od1 back)
    combine_kernel<<<Mrows, 256>>>(od0, od1, x, ln_g, ln_b, out);
}

// round 6
// speedup vs baseline: 1.7442x; 1.7390x over previous
#include <cuda_runtime.h>
#include <cuda_bf16.h>
#include <math.h>

// ---------------- problem constants ----------------
#define Bb 2
#define Ll 2048
#define DM 512
#define DI 1024
#define DS 16
#define DR 32
#define Mrows (Bb*Ll)          // 4096
#define NSLICE 8               // split-K slices for GEMM2
#define CT 8                   // scan prefetch chunk length

// ---------------- scratch (device globals; allocation-free) ----------------
__device__ float g_xz  [2][(size_t)Mrows*2*DI];
__device__ float g_xc  [2][(size_t)Mrows*DI];
__device__ float g_proj[2][(size_t)Mrows*64];
__device__ float g_pp  [2][NSLICE][(size_t)Mrows*64];
__device__ float g_dt  [2][(size_t)Mrows*DI];
__device__ float g_yg  [2][(size_t)Mrows*DI];
__device__ float g_od  [2][(size_t)Mrows*DM];

// ---------------- helpers ----------------
__device__ __forceinline__ float softplusf(float x) {
    return fmaxf(x, 0.f) + log1pf(__expf(-fabsf(x)));
}
__device__ __forceinline__ float siluf(float x) {
    return x / (1.f + __expf(-x));
}
__device__ __forceinline__ unsigned f2tf(float f) {
    unsigned u;
    asm("cvt.rna.tf32.f32 %0, %1;" : "=r"(u) : "f"(f));
    return u;
}
__device__ __forceinline__ void mma_tf32(float c[4], const unsigned a[4], const unsigned b[2]) {
    asm volatile(
        "mma.sync.aligned.m16n8k8.row.col.f32.tf32.tf32.f32 "
        "{%0,%1,%2,%3}, {%4,%5,%6,%7}, {%8,%9}, {%0,%1,%2,%3};\n"
        : "+f"(c[0]), "+f"(c[1]), "+f"(c[2]), "+f"(c[3])
        : "r"(a[0]), "r"(a[1]), "r"(a[2]), "r"(a[3]), "r"(b[0]), "r"(b[1]));
}
__device__ __forceinline__ void ldsm_x4(unsigned r[4], unsigned addr) {
    asm volatile("ldmatrix.sync.aligned.m8n8.x4.shared.b16 {%0,%1,%2,%3}, [%4];"
        : "=r"(r[0]), "=r"(r[1]), "=r"(r[2]), "=r"(r[3]) : "r"(addr));
}

// ---------------- param structs (2 directions) ----------------
struct GemmP {
    const float* A[2];
    const float* W[2];
    float*       C[2];
    const float* bias[2];
};
struct ConvP {
    const float* xz[2];
    float*       xc[2];
    const float* cw[2];
    const float* cb[2];
};
struct ScanP {
    const float* dt[2];
    const float* xc[2];
    const float* proj[2];
    const float* xz[2];
    const float* Alog[2];
    const float* Dsk[2];
    float*       yg[2];
};

// profiling-slot shifter (capture lands on 4th program launch)
__global__ void dummy_kernel() {}

// ================= tf32 tensor-core NT GEMM, ping-pong double buffer ==========
#define TG_BUF_WORDS (128*36*2)          // 9216 words per buffer (A then B)
#define TG_SMEM_BYTES (2*TG_BUF_WORDS*4) // 73728
template <int EPI>
__global__ __launch_bounds__(256, 2)
void tgemm_nt(GemmP p, int M, int N, int K, int lda, int ldb, int ldc) {
    extern __shared__ unsigned sm[];
    const int dir = blockIdx.z;
    const float* __restrict__ A = p.A[dir];
    const float* __restrict__ W = p.W[dir];
    float*       __restrict__ C = p.C[dir];
    const float* bias = p.bias[dir];

    const int cm = blockIdx.y * 128;
    const int cn = blockIdx.x * 128;

    const int t    = threadIdx.x;
    const int lane = t & 31;
    const int wid  = t >> 5;
    const int wm   = (wid >> 2) * 64;
    const int wn   = (wid & 3) * 32;
    const int l4   = lane >> 2;
    const int lm   = lane & 3;

    float acc[4][4][4];
#pragma unroll
    for (int mi = 0; mi < 4; mi++)
#pragma unroll
        for (int ni = 0; ni < 4; ni++)
#pragma unroll
            for (int r = 0; r < 4; r++) acc[mi][ni][r] = 0.f;

    const unsigned sBase = (unsigned)__cvta_generic_to_shared(sm);
    unsigned aAddr[4], bAddr[2];
    {
        int arw = (lane & 15), acl = (lane >> 4) * 4;
#pragma unroll
        for (int mi = 0; mi < 4; mi++)
            aAddr[mi] = sBase + (unsigned)(((wm + mi * 16 + arw) * 36 + acl) * 4);
        int brw = (lane & 7) + ((lane >> 4) * 8), bcl = ((lane >> 3) & 1) * 4;
#pragma unroll
        for (int j = 0; j < 2; j++)
            bAddr[j] = sBase + (unsigned)((4608 + (wn + j * 16 + brw) * 36 + bcl) * 4);
    }

    const int arow = t >> 2;
    const int acol = (t & 3) * 4;
    const float* Ap = A + (size_t)(cm + arow) * lda + acol;
    const float* Bp = W + (size_t)(cn + arow) * ldb + acol;
    const int sidx = arow * 36 + acol;

    {
        float4 a0 = *(const float4*)(Ap);
        float4 a1 = *(const float4*)(Ap + (size_t)64 * lda);
        float4 b0 = *(const float4*)(Bp);
        float4 b1 = *(const float4*)(Bp + (size_t)64 * ldb);
        uint4 u;
        u.x = f2tf(a0.x); u.y = f2tf(a0.y); u.z = f2tf(a0.z); u.w = f2tf(a0.w);
        *(uint4*)&sm[sidx] = u;
        u.x = f2tf(a1.x); u.y = f2tf(a1.y); u.z = f2tf(a1.z); u.w = f2tf(a1.w);
        *(uint4*)&sm[sidx + 64 * 36] = u;
        u.x = f2tf(b0.x); u.y = f2tf(b0.y); u.z = f2tf(b0.z); u.w = f2tf(b0.w);
        *(uint4*)&sm[4608 + sidx] = u;
        u.x = f2tf(b1.x); u.y = f2tf(b1.y); u.z = f2tf(b1.z); u.w = f2tf(b1.w);
        *(uint4*)&sm[4608 + sidx + 64 * 36] = u;
    }
    __syncthreads();

    int cur = 0;
    for (int k0 = 0; k0 < K; k0 += 16) {
        const bool more = (k0 + 16) < K;
        float4 na0, na1, nb0, nb1;
        if (more) {
            na0 = *(const float4*)(Ap + k0 + 16);
            na1 = *(const float4*)(Ap + (size_t)64 * lda + k0 + 16);
            nb0 = *(const float4*)(Bp + k0 + 16);
            nb1 = *(const float4*)(Bp + (size_t)64 * ldb + k0 + 16);
        }

        const unsigned boff = (unsigned)(cur * TG_BUF_WORDS * 4);
#pragma unroll
        for (int ks = 0; ks < 2; ks++) {
            const unsigned koff = boff + (unsigned)(ks * 32);
            unsigned af[4][4], bf[4][2];
#pragma unroll
            for (int mi = 0; mi < 4; mi++)
                ldsm_x4(af[mi], aAddr[mi] + koff);
            {
                unsigned r[4];
                ldsm_x4(r, bAddr[0] + koff);
                bf[0][0] = r[0]; bf[0][1] = r[1]; bf[1][0] = r[2]; bf[1][1] = r[3];
                ldsm_x4(r, bAddr[1] + koff);
                bf[2][0] = r[0]; bf[2][1] = r[1]; bf[3][0] = r[2]; bf[3][1] = r[3];
            }
#pragma unroll
            for (int mi = 0; mi < 4; mi++)
#pragma unroll
                for (int ni = 0; ni < 4; ni++)
                    mma_tf32(acc[mi][ni], af[mi], bf[ni]);
        }

        if (more) {
            unsigned* dst = sm + (1 - cur) * TG_BUF_WORDS;
            uint4 u;
            u.x = f2tf(na0.x); u.y = f2tf(na0.y); u.z = f2tf(na0.z); u.w = f2tf(na0.w);
            *(uint4*)&dst[sidx] = u;
            u.x = f2tf(na1.x); u.y = f2tf(na1.y); u.z = f2tf(na1.z); u.w = f2tf(na1.w);
            *(uint4*)&dst[sidx + 64 * 36] = u;
            u.x = f2tf(nb0.x); u.y = f2tf(nb0.y); u.z = f2tf(nb0.z); u.w = f2tf(nb0.w);
            *(uint4*)&dst[4608 + sidx] = u;
            u.x = f2tf(nb1.x); u.y = f2tf(nb1.y); u.z = f2tf(nb1.z); u.w = f2tf(nb1.w);
            *(uint4*)&dst[4608 + sidx + 64 * 36] = u;
        }
        __syncthreads();
        cur ^= 1;
    }

#pragma unroll
    for (int mi = 0; mi < 4; mi++) {
#pragma unroll
        for (int ni = 0; ni < 4; ni++) {
            int row = cm + wm + mi * 16 + l4;
            int col = cn + wn + ni * 8 + 2 * lm;
            float v0 = acc[mi][ni][0], v1 = acc[mi][ni][1];
            float v2 = acc[mi][ni][2], v3 = acc[mi][ni][3];
            if (EPI == 1) {
                float b0 = bias[col], b1 = bias[col + 1];
                v0 = softplusf(v0 + b0); v1 = softplusf(v1 + b1);
                v2 = softplusf(v2 + b0); v3 = softplusf(v3 + b1);
            }
            *(float2*)(C + (size_t)row * ldc + col)       = make_float2(v0, v1);
            *(float2*)(C + (size_t)(row + 8) * ldc + col) = make_float2(v2, v3);
        }
    }
}

// ================= fp32 SGEMM (kept for GEMM2 split-K, TN=64) =================
template <int TN, int EPI>
__global__ __launch_bounds__(256, 2)
void sgemm_nt(GemmP p, int M, int N, int K, int lda, int ldb, int ldc) {
    const int dir = blockIdx.z;
    const float* __restrict__ A = p.A[dir];
    const float* __restrict__ W = p.W[dir];
    float*       __restrict__ C = p.C[dir];

    const int cm = blockIdx.y * 128;
    int cn;
    if (EPI == 2) {
        cn = 0;
        A += (size_t)blockIdx.x * K;
        W += (size_t)blockIdx.x * K;
        C += (size_t)blockIdx.x * (size_t)M * ldc;
    } else {
        cn = blockIdx.x * TN;
    }

    __shared__ float As[16][128];
    __shared__ float Bs[16][TN];

    constexpr int WN = TN / 16;
    float acc[8][WN];
#pragma unroll
    for (int i = 0; i < 8; i++)
#pragma unroll
        for (int j = 0; j < WN; j++) acc[i][j] = 0.f;

    const int t  = threadIdx.x;
    const int tr = t >> 4;
    const int tc = t & 15;

    const int ar0 = (t * 2)     >> 2, ak0 = ((t * 2)     & 3) * 4;
    const int ar1 = (t * 2 + 1) >> 2, ak1 = ((t * 2 + 1) & 3) * 4;
    const int br0 = (TN == 128) ? ar0 : (t >> 2);
    const int bk0 = (TN == 128) ? ak0 : ((t & 3) * 4);

    const float* Ap0 = A + (size_t)(cm + ar0) * lda + ak0;
    const float* Ap1 = A + (size_t)(cm + ar1) * lda + ak1;
    const float* Bp0 = W + (size_t)(cn + br0) * ldb + bk0;
    const float* Bp1 = (TN == 128) ? (W + (size_t)(cn + ar1) * ldb + ak1) : nullptr;

    float4 sa0 = *(const float4*)Ap0;
    float4 sa1 = *(const float4*)Ap1;
    float4 sb0 = *(const float4*)Bp0;
    float4 sb1 = (TN == 128) ? *(const float4*)Bp1 : make_float4(0, 0, 0, 0);

    for (int k0 = 0; k0 < K; k0 += 16) {
        As[ak0 + 0][ar0] = sa0.x; As[ak0 + 1][ar0] = sa0.y;
        As[ak0 + 2][ar0] = sa0.z; As[ak0 + 3][ar0] = sa0.w;
        As[ak1 + 0][ar1] = sa1.x; As[ak1 + 1][ar1] = sa1.y;
        As[ak1 + 2][ar1] = sa1.z; As[ak1 + 3][ar1] = sa1.w;
        Bs[bk0 + 0][br0] = sb0.x; Bs[bk0 + 1][br0] = sb0.y;
        Bs[bk0 + 2][br0] = sb0.z; Bs[bk0 + 3][br0] = sb0.w;
        if (TN == 128) {
            Bs[ak1 + 0][ar1] = sb1.x; Bs[ak1 + 1][ar1] = sb1.y;
            Bs[ak1 + 2][ar1] = sb1.z; Bs[ak1 + 3][ar1] = sb1.w;
        }
        __syncthreads();

        if (k0 + 16 < K) {
            sa0 = *(const float4*)(Ap0 + k0 + 16);
            sa1 = *(const float4*)(Ap1 + k0 + 16);
            sb0 = *(const float4*)(Bp0 + k0 + 16);
            if (TN == 128) sb1 = *(const float4*)(Bp1 + k0 + 16);
        }

#pragma unroll
        for (int k = 0; k < 16; k++) {
            float a[8], bq[WN];
            *(float4*)&a[0] = *(const float4*)&As[k][tr * 8];
            *(float4*)&a[4] = *(const float4*)&As[k][tr * 8 + 4];
            *(float4*)&bq[0] = *(const float4*)&Bs[k][tc * WN];
            if (TN == 128)
                *(float4*)&bq[4] = *(const float4*)&Bs[k][tc * WN + 4];
#pragma unroll
            for (int i = 0; i < 8; i++)
#pragma unroll
                for (int j = 0; j < WN; j++)
                    acc[i][j] = fmaf(a[i], bq[j], acc[i][j]);
        }
        __syncthreads();
    }

#pragma unroll
    for (int i = 0; i < 8; i++) {
        int row = cm + tr * 8 + i;
        float* Crow = C + (size_t)row * ldc + cn + tc * WN;
        float4 v0 = make_float4(acc[i][0], acc[i][1], acc[i][2], acc[i][3]);
        *(float4*)(Crow) = v0;
        if (TN == 128) {
            float4 v1 = make_float4(acc[i][4], acc[i][5], acc[i][6], acc[i][7]);
            *(float4*)(Crow + 4) = v1;
        }
    }
}

// ---------------- split-K reduction for proj ----------------
__global__ void reduce_proj_kernel(const float* __restrict__ part,
                                   float* __restrict__ proj) {
    int i = blockIdx.x * blockDim.x + threadIdx.x;
    const int per = Mrows * 64;
    if (i >= 2 * per) return;
    int dirn = i / per;
    int off  = i - dirn * per;
    const float* b = part + (size_t)dirn * NSLICE * per + off;
    float s = 0.f;
#pragma unroll
    for (int sidx = 0; sidx < NSLICE; sidx++)
        s += b[(size_t)sidx * per];
    proj[(size_t)dirn * per + off] = s;
}

// ---------------- causal depthwise conv(4) + bias + silu (dir1 reads flipped) ---
__global__ void conv_silu_kernel(ConvP p) {
    const int dir = blockIdx.y;
    const float* __restrict__ xz = p.xz[dir];
    float*       __restrict__ xc = p.xc[dir];
    const float* __restrict__ cw = p.cw[dir];
    const float* __restrict__ cb = p.cb[dir];

    int i = blockIdx.x * blockDim.x + threadIdx.x;
    if (i >= Mrows * DI) return;
    int d  = i & (DI - 1);
    int bl = i >> 10;
    int l  = bl & (Ll - 1);
    int b  = bl >> 11;

    float w0 = cw[d * 4 + 0], w1 = cw[d * 4 + 1], w2 = cw[d * 4 + 2], w3 = cw[d * 4 + 3];
    float s = cb[d];
#pragma unroll
    for (int k = 0; k < 4; k++) {
        int j = l - 3 + k;
        if (j >= 0) {
            int pr = (dir == 0) ? j : (Ll - 1 - j);
            float wv = (k == 0) ? w0 : (k == 1) ? w1 : (k == 2) ? w2 : w3;
            s = fmaf(xz[((size_t)b * Ll + pr) * (2 * DI) + d], wv, s);
        }
    }
    xc[i] = siluf(s);
}

// ---------------- selective scan, chunked deep prefetch (CT=8) ----------------
__global__ void scan_kernel(ScanP p) {
    const int dir = blockIdx.y;
    const float* __restrict__ dt   = p.dt[dir];
    const float* __restrict__ xc   = p.xc[dir];
    const float* __restrict__ proj = p.proj[dir];
    const float* __restrict__ xz   = p.xz[dir];
    const float* __restrict__ Alog = p.Alog[dir];
    const float* __restrict__ Dsk  = p.Dsk[dir];
    float*       __restrict__ yg   = p.yg[dir];

    int tid = blockIdx.x * blockDim.x + threadIdx.x;
    int grp = tid >> 4;
    int n   = tid & 15;
    int b = grp >> 10;
    int d = grp & (DI - 1);

    const float Ad = -__expf(Alog[d * DS + n]);
    const float Dv = Dsk[d];
    float h = 0.f;

    const float* pdt = dt   + ((size_t)b * Ll) * DI + d;
    const float* pxc = xc   + ((size_t)b * Ll) * DI + d;
    const float* pBC = proj + ((size_t)b * Ll) * 64;
    const ptrdiff_t zs = (dir == 0) ? (ptrdiff_t)(2 * DI) : -(ptrdiff_t)(2 * DI);
    const float* pz = (dir == 0)
        ? xz + ((size_t)b * Ll) * (2 * DI) + DI + d
        : xz + ((size_t)b * Ll + (Ll - 1)) * (2 * DI) + DI + d;
    float* pyg = yg + ((size_t)b * Ll) * DI + d;

    float cdt[CT], cu[CT], cB[CT], cC[CT], cz[CT];
#pragma unroll
    for (int i = 0; i < CT; i++) {
        cdt[i] = pdt[(size_t)i * DI];
        cu[i]  = pxc[(size_t)i * DI];
        cB[i]  = pBC[(size_t)i * 64 + 32 + n];
        cC[i]  = pBC[(size_t)i * 64 + 48 + n];
        cz[i]  = pz[(ptrdiff_t)i * zs];
    }

    for (int c = 0; c < Ll / CT; c++) {
        float ndt[CT], nu[CT], nB[CT], nC[CT], nz[CT];
        const int nbase = (c + 1) * CT;
        if (c + 1 < Ll / CT) {
#pragma unroll
            for (int i = 0; i < CT; i++) {
                ndt[i] = pdt[(size_t)(nbase + i) * DI];
                nu[i]  = pxc[(size_t)(nbase + i) * DI];
                nB[i]  = pBC[(size_t)(nbase + i) * 64 + 32 + n];
                nC[i]  = pBC[(size_t)(nbase + i) * 64 + 48 + n];
                nz[i]  = pz[(ptrdiff_t)(nbase + i) * zs];
            }
        }
#pragma unroll
        for (int i = 0; i < CT; i++) {
            float dA = __expf(cdt[i] * Ad);
            h = fmaf(dA, h, cdt[i] * cB[i] * cu[i]);
            float y = h * cC[i];
            y += __shfl_xor_sync(0xffffffffu, y, 8);
            y += __shfl_xor_sync(0xffffffffu, y, 4);
            y += __shfl_xor_sync(0xffffffffu, y, 2);
            y += __shfl_xor_sync(0xffffffffu, y, 1);
            if (n == 0)
                pyg[(size_t)(c * CT + i) * DI] = (y + cu[i] * Dv) * siluf(cz[i]);
        }
#pragma unroll
        for (int i = 0; i < CT; i++) {
            cdt[i] = ndt[i]; cu[i] = nu[i]; cB[i] = nB[i];
            cC[i] = nC[i];   cz[i] = nz[i];
        }
    }
}

// ---------------- combine fw + flipped bw, LayerNorm, silu + residual ----------
__global__ void combine_kernel(const float* __restrict__ f,
                               const float* __restrict__ bw,
                               const float* __restrict__ x,
                               const float* __restrict__ g,
                               const float* __restrict__ beta,
                               float* __restrict__ out) {
    int row = blockIdx.x;
    int b = row >> 11;
    int l = row & (Ll - 1);
    const float* fr = f  + (size_t)row * DM;
    const float* br = bw + ((size_t)b * Ll + (Ll - 1 - l)) * DM;

    int c0 = threadIdx.x;
    int c1 = threadIdx.x + 256;
    float v0 = 0.5f * (fr[c0] + br[c0]);
    float v1 = 0.5f * (fr[c1] + br[c1]);

    float s1 = v0 + v1;
    float s2 = v0 * v0 + v1 * v1;
#pragma unroll
    for (int o = 16; o; o >>= 1) {
        s1 += __shfl_xor_sync(0xffffffffu, s1, o);
        s2 += __shfl_xor_sync(0xffffffffu, s2, o);
    }
    __shared__ float sh1[8], sh2[8];
    __shared__ float s_mu, s_rstd;
    int w = threadIdx.x >> 5, ln = threadIdx.x & 31;
    if (ln == 0) { sh1[w] = s1; sh2[w] = s2; }
    __syncthreads();
    if (threadIdx.x == 0) {
        float a = 0.f, q = 0.f;
#pragma unroll
        for (int i = 0; i < 8; i++) { a += sh1[i]; q += sh2[i]; }
        float mu  = a * (1.f / DM);
        float var = q * (1.f / DM) - mu * mu;
        s_mu   = mu;
        s_rstd = rsqrtf(var + 1e-5f);
    }
    __syncthreads();
    float mu = s_mu, rstd = s_rstd;
    const float* xr = x + (size_t)row * DM;
    float o0 = (v0 - mu) * rstd * g[c0] + beta[c0];
    float o1 = (v1 - mu) * rstd * g[c1] + beta[c1];
    out[(size_t)row * DM + c0] = siluf(o0) + xr[c0];
    out[(size_t)row * DM + c1] = siluf(o1) + xr[c1];
}

// ---------------- launch ----------------
extern "C" void kernel_launch(void* const* d_in, const int* in_sizes, int n_in,
                              void* d_out, int out_size) {
    const float* x = (const float*)d_in[0];
    const float* fW_in  = (const float*)d_in[1];
    const float* fcw    = (const float*)d_in[2];
    const float* fcb    = (const float*)d_in[3];
    const float* fWxp   = (const float*)d_in[4];
    const float* fWdt   = (const float*)d_in[5];
    const float* fbdt   = (const float*)d_in[6];
    const float* fAlog  = (const float*)d_in[7];
    const float* fDsk   = (const float*)d_in[8];
    const float* fWout  = (const float*)d_in[9];
    const float* bW_in  = (const float*)d_in[10];
    const float* bcw    = (const float*)d_in[11];
    const float* bcb    = (const float*)d_in[12];
    const float* bWxp   = (const float*)d_in[13];
    const float* bWdt   = (const float*)d_in[14];
    const float* bbdt   = (const float*)d_in[15];
    const float* bAlog  = (const float*)d_in[16];
    const float* bDsk   = (const float*)d_in[17];
    const float* bWout  = (const float*)d_in[18];
    const float* ln_g   = (const float*)d_in[19];
    const float* ln_b   = (const float*)d_in[20];
    float* out = (float*)d_out;

    float *xz, *xc, *proj, *pp, *dtb, *ygb, *od;
    cudaGetSymbolAddress((void**)&xz,   g_xz);
    cudaGetSymbolAddress((void**)&xc,   g_xc);
    cudaGetSymbolAddress((void**)&proj, g_proj);
    cudaGetSymbolAddress((void**)&pp,   g_pp);
    cudaGetSymbolAddress((void**)&dtb,  g_dt);
    cudaGetSymbolAddress((void**)&ygb,  g_yg);
    cudaGetSymbolAddress((void**)&od,   g_od);

    const size_t SXZ = (size_t)Mrows * 2 * DI;
    const size_t SXC = (size_t)Mrows * DI;
    const size_t SPJ = (size_t)Mrows * 64;
    const size_t SOD = (size_t)Mrows * DM;

    float* xz0 = xz;   float* xz1 = xz + SXZ;
    float* xc0 = xc;   float* xc1 = xc + SXC;
    float* pj0 = proj; float* pj1 = proj + SPJ;
    float* pp0 = pp;   float* pp1 = pp + (size_t)NSLICE * SPJ;
    float* dt0 = dtb;  float* dt1 = dtb + SXC;
    float* yg0 = ygb;  float* yg1 = ygb + SXC;
    float* od0 = od;   float* od1 = od + SOD;

    cudaFuncSetAttribute(tgemm_nt<0>, cudaFuncAttributeMaxDynamicSharedMemorySize, TG_SMEM_BYTES);
    cudaFuncSetAttribute(tgemm_nt<1>, cudaFuncAttributeMaxDynamicSharedMemorySize, TG_SMEM_BYTES);

    // 0a-0c: keep ncu capture slot on tgemm1 (4th launch)
    dummy_kernel<<<1, 32>>>();
    dummy_kernel<<<1, 32>>>();
    dummy_kernel<<<1, 32>>>();

    // 1. GEMM1 (tf32): xz' = x * W_in^T
    {
        GemmP p;
        p.A[0] = x;     p.A[1] = x;
        p.W[0] = fW_in; p.W[1] = bW_in;
        p.C[0] = xz0;   p.C[1] = xz1;
        p.bias[0] = nullptr; p.bias[1] = nullptr;
        dim3 grid(2 * DI / 128, Mrows / 128, 2);
        tgemm_nt<0><<<grid, 256, TG_SMEM_BYTES>>>(p, Mrows, 2 * DI, DM, DM, DM, 2 * DI);
    }

    // 2. conv + silu
    {
        ConvP p;
        p.xz[0] = xz0; p.xz[1] = xz1;
        p.xc[0] = xc0; p.xc[1] = xc1;
        p.cw[0] = fcw; p.cw[1] = bcw;
        p.cb[0] = fcb; p.cb[1] = bcb;
        dim3 grid((Mrows * DI + 255) / 256, 2);
        conv_silu_kernel<<<grid, 256>>>(p);
    }

    // 3. GEMM2 split-K (fp32)
    {
        GemmP p;
        p.A[0] = xc0;  p.A[1] = xc1;
        p.W[0] = fWxp; p.W[1] = bWxp;
        p.C[0] = pp0;  p.C[1] = pp1;
        p.bias[0] = nullptr; p.bias[1] = nullptr;
        dim3 grid(NSLICE, Mrows / 128, 2);
        sgemm_nt<64, 2><<<grid, 256>>>(p, Mrows, 64, DI / NSLICE, DI, DI, 64);
    }

    // 4. reduce split-K partials
    reduce_proj_kernel<<<(2 * Mrows * 64 + 255) / 256, 256>>>(pp, proj);

    // 5. GEMM3 (tf32): dt = softplus(dtpart * Wdt^T + b_dt)
    {
        GemmP p;
        p.A[0] = pj0;  p.A[1] = pj1;
        p.W[0] = fWdt; p.W[1] = bWdt;
        p.C[0] = dt0;  p.C[1] = dt1;
        p.bias[0] = fbdt; p.bias[1] = bbdt;
        dim3 grid(DI / 128, Mrows / 128, 2);
        tgemm_nt<1><<<grid, 256, TG_SMEM_BYTES>>>(p, Mrows, DI, DR, 64, DR, DI);
    }

    // 6. scan (+ D skip + z gate)
    {
        ScanP p;
        p.dt[0] = dt0;   p.dt[1] = dt1;
        p.xc[0] = xc0;   p.xc[1] = xc1;
        p.proj[0] = pj0; p.proj[1] = pj1;
        p.xz[0] = xz0;   p.xz[1] = xz1;
        p.Alog[0] = fAlog; p.Alog[1] = bAlog;
        p.Dsk[0] = fDsk;   p.Dsk[1] = bDsk;
        p.yg[0] = yg0;   p.yg[1] = yg1;
        dim3 grid((Bb * DI * DS) / 256, 2);
        scan_kernel<<<grid, 256>>>(p);
    }

    // 7. GEMM4 (tf32): od = yg * Wout^T
    {
        GemmP p;
        p.A[0] = yg0;   p.A[1] = yg1;
        p.W[0] = fWout; p.W[1] = bWout;
        p.C[0] = od0;   p.C[1] = od1;
        p.bias[0] = nullptr; p.bias[1] = nullptr;
        dim3 grid(DM / 128, Mrows / 128, 2);
        tgemm_nt<0><<<grid, 256, TG_SMEM_BYTES>>>(p, Mrows, DM, DI, DI, DI, DM);
    }

    // 8. combine + LN + silu + residual
    combine_kernel<<<Mrows, 256>>>(od0, od1, x, ln_g, ln_b, out);
}

// round 7
// speedup vs baseline: 1.9342x; 1.1090x over previous
#include <cuda_runtime.h>
#include <cuda_bf16.h>
#include <math.h>

// ---------------- problem constants ----------------
#define Bb 2
#define Ll 2048
#define DM 512
#define DI 1024
#define DS 16
#define DR 32
#define Mrows (Bb*Ll)          // 4096
#define NSLICE 8               // split-K slices for GEMM2
#define CT 8                   // scan prefetch chunk length

// ---------------- scratch (device globals; allocation-free) ----------------
__device__ float g_xz  [2][(size_t)Mrows*2*DI];
__device__ float g_xc  [2][(size_t)Mrows*DI];
__device__ float g_proj[2][(size_t)Mrows*64];
__device__ float g_pp  [2][NSLICE][(size_t)Mrows*64];
__device__ float g_dt  [2][(size_t)Mrows*DI];
__device__ float g_yg  [2][(size_t)Mrows*DI];
__device__ float g_od  [2][(size_t)Mrows*DM];

// ---------------- helpers ----------------
__device__ __forceinline__ float softplusf(float x) {
    return fmaxf(x, 0.f) + log1pf(__expf(-fabsf(x)));
}
__device__ __forceinline__ float siluf(float x) {
    return x / (1.f + __expf(-x));
}
__device__ __forceinline__ unsigned f2tf(float f) {
    unsigned u;
    asm("cvt.rna.tf32.f32 %0, %1;" : "=r"(u) : "f"(f));
    return u;
}
__device__ __forceinline__ void mma_tf32(float c[4], const unsigned a[4], const unsigned b[2]) {
    asm volatile(
        "mma.sync.aligned.m16n8k8.row.col.f32.tf32.tf32.f32 "
        "{%0,%1,%2,%3}, {%4,%5,%6,%7}, {%8,%9}, {%0,%1,%2,%3};\n"
        : "+f"(c[0]), "+f"(c[1]), "+f"(c[2]), "+f"(c[3])
        : "r"(a[0]), "r"(a[1]), "r"(a[2]), "r"(a[3]), "r"(b[0]), "r"(b[1]));
}
__device__ __forceinline__ void ldsm_x4(unsigned r[4], unsigned addr) {
    asm volatile("ldmatrix.sync.aligned.m8n8.x4.shared.b16 {%0,%1,%2,%3}, [%4];"
        : "=r"(r[0]), "=r"(r[1]), "=r"(r[2]), "=r"(r[3]) : "r"(addr));
}

// ---------------- param structs (2 directions) ----------------
struct GemmP {
    const float* A[2];
    const float* W[2];
    float*       C[2];
    const float* bias[2];
};
struct ConvP {
    const float* xz[2];
    float*       xc[2];
    const float* cw[2];
    const float* cb[2];
};
struct ScanP {
    const float* dt[2];
    const float* xc[2];
    const float* proj[2];
    const float* xz[2];
    const float* Alog[2];
    const float* Dsk[2];
    float*       yg[2];
};

// profiling-slot shifter (capture lands on 4th program launch)
__global__ void dummy_kernel() {}

// ================= tf32 tensor-core NT GEMM, ping-pong double buffer ==========
#define TG_BUF_WORDS (128*36*2)          // 9216 words per buffer (A then B)
#define TG_SMEM_BYTES (2*TG_BUF_WORDS*4) // 73728
template <int EPI>
__global__ __launch_bounds__(256, 2)
void tgemm_nt(GemmP p, int M, int N, int K, int lda, int ldb, int ldc) {
    extern __shared__ unsigned sm[];
    const int dir = blockIdx.z;
    const float* __restrict__ A = p.A[dir];
    const float* __restrict__ W = p.W[dir];
    float*       __restrict__ C = p.C[dir];
    const float* bias = p.bias[dir];

    const int cm = blockIdx.y * 128;
    const int cn = blockIdx.x * 128;

    const int t    = threadIdx.x;
    const int lane = t & 31;
    const int wid  = t >> 5;
    const int wm   = (wid >> 2) * 64;
    const int wn   = (wid & 3) * 32;
    const int l4   = lane >> 2;
    const int lm   = lane & 3;

    float acc[4][4][4];
#pragma unroll
    for (int mi = 0; mi < 4; mi++)
#pragma unroll
        for (int ni = 0; ni < 4; ni++)
#pragma unroll
            for (int r = 0; r < 4; r++) acc[mi][ni][r] = 0.f;

    const unsigned sBase = (unsigned)__cvta_generic_to_shared(sm);
    unsigned aAddr[4], bAddr[2];
    {
        int arw = (lane & 15), acl = (lane >> 4) * 4;
#pragma unroll
        for (int mi = 0; mi < 4; mi++)
            aAddr[mi] = sBase + (unsigned)(((wm + mi * 16 + arw) * 36 + acl) * 4);
        int brw = (lane & 7) + ((lane >> 4) * 8), bcl = ((lane >> 3) & 1) * 4;
#pragma unroll
        for (int j = 0; j < 2; j++)
            bAddr[j] = sBase + (unsigned)((4608 + (wn + j * 16 + brw) * 36 + bcl) * 4);
    }

    const int arow = t >> 2;
    const int acol = (t & 3) * 4;
    const float* Ap = A + (size_t)(cm + arow) * lda + acol;
    const float* Bp = W + (size_t)(cn + arow) * ldb + acol;
    const int sidx = arow * 36 + acol;

    {
        float4 a0 = *(const float4*)(Ap);
        float4 a1 = *(const float4*)(Ap + (size_t)64 * lda);
        float4 b0 = *(const float4*)(Bp);
        float4 b1 = *(const float4*)(Bp + (size_t)64 * ldb);
        uint4 u;
        u.x = f2tf(a0.x); u.y = f2tf(a0.y); u.z = f2tf(a0.z); u.w = f2tf(a0.w);
        *(uint4*)&sm[sidx] = u;
        u.x = f2tf(a1.x); u.y = f2tf(a1.y); u.z = f2tf(a1.z); u.w = f2tf(a1.w);
        *(uint4*)&sm[sidx + 64 * 36] = u;
        u.x = f2tf(b0.x); u.y = f2tf(b0.y); u.z = f2tf(b0.z); u.w = f2tf(b0.w);
        *(uint4*)&sm[4608 + sidx] = u;
        u.x = f2tf(b1.x); u.y = f2tf(b1.y); u.z = f2tf(b1.z); u.w = f2tf(b1.w);
        *(uint4*)&sm[4608 + sidx + 64 * 36] = u;
    }
    __syncthreads();

    int cur = 0;
    for (int k0 = 0; k0 < K; k0 += 16) {
        const bool more = (k0 + 16) < K;
        float4 na0, na1, nb0, nb1;
        if (more) {
            na0 = *(const float4*)(Ap + k0 + 16);
            na1 = *(const float4*)(Ap + (size_t)64 * lda + k0 + 16);
            nb0 = *(const float4*)(Bp + k0 + 16);
            nb1 = *(const float4*)(Bp + (size_t)64 * ldb + k0 + 16);
        }

        const unsigned boff = (unsigned)(cur * TG_BUF_WORDS * 4);
#pragma unroll
        for (int ks = 0; ks < 2; ks++) {
            const unsigned koff = boff + (unsigned)(ks * 32);
            unsigned af[4][4], bf[4][2];
#pragma unroll
            for (int mi = 0; mi < 4; mi++)
                ldsm_x4(af[mi], aAddr[mi] + koff);
            {
                unsigned r[4];
                ldsm_x4(r, bAddr[0] + koff);
                bf[0][0] = r[0]; bf[0][1] = r[1]; bf[1][0] = r[2]; bf[1][1] = r[3];
                ldsm_x4(r, bAddr[1] + koff);
                bf[2][0] = r[0]; bf[2][1] = r[1]; bf[3][0] = r[2]; bf[3][1] = r[3];
            }
#pragma unroll
            for (int mi = 0; mi < 4; mi++)
#pragma unroll
                for (int ni = 0; ni < 4; ni++)
                    mma_tf32(acc[mi][ni], af[mi], bf[ni]);
        }

        if (more) {
            unsigned* dst = sm + (1 - cur) * TG_BUF_WORDS;
            uint4 u;
            u.x = f2tf(na0.x); u.y = f2tf(na0.y); u.z = f2tf(na0.z); u.w = f2tf(na0.w);
            *(uint4*)&dst[sidx] = u;
            u.x = f2tf(na1.x); u.y = f2tf(na1.y); u.z = f2tf(na1.z); u.w = f2tf(na1.w);
            *(uint4*)&dst[sidx + 64 * 36] = u;
            u.x = f2tf(nb0.x); u.y = f2tf(nb0.y); u.z = f2tf(nb0.z); u.w = f2tf(nb0.w);
            *(uint4*)&dst[4608 + sidx] = u;
            u.x = f2tf(nb1.x); u.y = f2tf(nb1.y); u.z = f2tf(nb1.z); u.w = f2tf(nb1.w);
            *(uint4*)&dst[4608 + sidx + 64 * 36] = u;
        }
        __syncthreads();
        cur ^= 1;
    }

#pragma unroll
    for (int mi = 0; mi < 4; mi++) {
#pragma unroll
        for (int ni = 0; ni < 4; ni++) {
            int row = cm + wm + mi * 16 + l4;
            int col = cn + wn + ni * 8 + 2 * lm;
            float v0 = acc[mi][ni][0], v1 = acc[mi][ni][1];
            float v2 = acc[mi][ni][2], v3 = acc[mi][ni][3];
            if (EPI == 1) {
                float b0 = bias[col], b1 = bias[col + 1];
                v0 = softplusf(v0 + b0); v1 = softplusf(v1 + b1);
                v2 = softplusf(v2 + b0); v3 = softplusf(v3 + b1);
            }
            *(float2*)(C + (size_t)row * ldc + col)       = make_float2(v0, v1);
            *(float2*)(C + (size_t)(row + 8) * ldc + col) = make_float2(v2, v3);
        }
    }
}

// ================= fp32 SGEMM (kept for GEMM2 split-K, TN=64) =================
template <int TN, int EPI>
__global__ __launch_bounds__(256, 2)
void sgemm_nt(GemmP p, int M, int N, int K, int lda, int ldb, int ldc) {
    const int dir = blockIdx.z;
    const float* __restrict__ A = p.A[dir];
    const float* __restrict__ W = p.W[dir];
    float*       __restrict__ C = p.C[dir];

    const int cm = blockIdx.y * 128;
    int cn;
    if (EPI == 2) {
        cn = 0;
        A += (size_t)blockIdx.x * K;
        W += (size_t)blockIdx.x * K;
        C += (size_t)blockIdx.x * (size_t)M * ldc;
    } else {
        cn = blockIdx.x * TN;
    }

    __shared__ float As[16][128];
    __shared__ float Bs[16][TN];

    constexpr int WN = TN / 16;
    float acc[8][WN];
#pragma unroll
    for (int i = 0; i < 8; i++)
#pragma unroll
        for (int j = 0; j < WN; j++) acc[i][j] = 0.f;

    const int t  = threadIdx.x;
    const int tr = t >> 4;
    const int tc = t & 15;

    const int ar0 = (t * 2)     >> 2, ak0 = ((t * 2)     & 3) * 4;
    const int ar1 = (t * 2 + 1) >> 2, ak1 = ((t * 2 + 1) & 3) * 4;
    const int br0 = (TN == 128) ? ar0 : (t >> 2);
    const int bk0 = (TN == 128) ? ak0 : ((t & 3) * 4);

    const float* Ap0 = A + (size_t)(cm + ar0) * lda + ak0;
    const float* Ap1 = A + (size_t)(cm + ar1) * lda + ak1;
    const float* Bp0 = W + (size_t)(cn + br0) * ldb + bk0;
    const float* Bp1 = (TN == 128) ? (W + (size_t)(cn + ar1) * ldb + ak1) : nullptr;

    float4 sa0 = *(const float4*)Ap0;
    float4 sa1 = *(const float4*)Ap1;
    float4 sb0 = *(const float4*)Bp0;
    float4 sb1 = (TN == 128) ? *(const float4*)Bp1 : make_float4(0, 0, 0, 0);

    for (int k0 = 0; k0 < K; k0 += 16) {
        As[ak0 + 0][ar0] = sa0.x; As[ak0 + 1][ar0] = sa0.y;
        As[ak0 + 2][ar0] = sa0.z; As[ak0 + 3][ar0] = sa0.w;
        As[ak1 + 0][ar1] = sa1.x; As[ak1 + 1][ar1] = sa1.y;
        As[ak1 + 2][ar1] = sa1.z; As[ak1 + 3][ar1] = sa1.w;
        Bs[bk0 + 0][br0] = sb0.x; Bs[bk0 + 1][br0] = sb0.y;
        Bs[bk0 + 2][br0] = sb0.z; Bs[bk0 + 3][br0] = sb0.w;
        if (TN == 128) {
            Bs[ak1 + 0][ar1] = sb1.x; Bs[ak1 + 1][ar1] = sb1.y;
            Bs[ak1 + 2][ar1] = sb1.z; Bs[ak1 + 3][ar1] = sb1.w;
        }
        __syncthreads();

        if (k0 + 16 < K) {
            sa0 = *(const float4*)(Ap0 + k0 + 16);
            sa1 = *(const float4*)(Ap1 + k0 + 16);
            sb0 = *(const float4*)(Bp0 + k0 + 16);
            if (TN == 128) sb1 = *(const float4*)(Bp1 + k0 + 16);
        }

#pragma unroll
        for (int k = 0; k < 16; k++) {
            float a[8], bq[WN];
            *(float4*)&a[0] = *(const float4*)&As[k][tr * 8];
            *(float4*)&a[4] = *(const float4*)&As[k][tr * 8 + 4];
            *(float4*)&bq[0] = *(const float4*)&Bs[k][tc * WN];
            if (TN == 128)
                *(float4*)&bq[4] = *(const float4*)&Bs[k][tc * WN + 4];
#pragma unroll
            for (int i = 0; i < 8; i++)
#pragma unroll
                for (int j = 0; j < WN; j++)
                    acc[i][j] = fmaf(a[i], bq[j], acc[i][j]);
        }
        __syncthreads();
    }

#pragma unroll
    for (int i = 0; i < 8; i++) {
        int row = cm + tr * 8 + i;
        float* Crow = C + (size_t)row * ldc + cn + tc * WN;
        float4 v0 = make_float4(acc[i][0], acc[i][1], acc[i][2], acc[i][3]);
        *(float4*)(Crow) = v0;
        if (TN == 128) {
            float4 v1 = make_float4(acc[i][4], acc[i][5], acc[i][6], acc[i][7]);
            *(float4*)(Crow + 4) = v1;
        }
    }
}

// ---------------- split-K reduction for proj ----------------
__global__ void reduce_proj_kernel(const float* __restrict__ part,
                                   float* __restrict__ proj) {
    int i = blockIdx.x * blockDim.x + threadIdx.x;
    const int per = Mrows * 64;
    if (i >= 2 * per) return;
    int dirn = i / per;
    int off  = i - dirn * per;
    const float* b = part + (size_t)dirn * NSLICE * per + off;
    float s = 0.f;
#pragma unroll
    for (int sidx = 0; sidx < NSLICE; sidx++)
        s += b[(size_t)sidx * per];
    proj[(size_t)dirn * per + off] = s;
}

// ---------------- causal depthwise conv(4) + bias + silu (dir1 reads flipped) ---
__global__ void conv_silu_kernel(ConvP p) {
    const int dir = blockIdx.y;
    const float* __restrict__ xz = p.xz[dir];
    float*       __restrict__ xc = p.xc[dir];
    const float* __restrict__ cw = p.cw[dir];
    const float* __restrict__ cb = p.cb[dir];

    int i = blockIdx.x * blockDim.x + threadIdx.x;
    if (i >= Mrows * DI) return;
    int d  = i & (DI - 1);
    int bl = i >> 10;
    int l  = bl & (Ll - 1);
    int b  = bl >> 11;

    float w0 = cw[d * 4 + 0], w1 = cw[d * 4 + 1], w2 = cw[d * 4 + 2], w3 = cw[d * 4 + 3];
    float s = cb[d];
#pragma unroll
    for (int k = 0; k < 4; k++) {
        int j = l - 3 + k;
        if (j >= 0) {
            int pr = (dir == 0) ? j : (Ll - 1 - j);
            float wv = (k == 0) ? w0 : (k == 1) ? w1 : (k == 2) ? w2 : w3;
            s = fmaf(xz[((size_t)b * Ll + pr) * (2 * DI) + d], wv, s);
        }
    }
    xc[i] = siluf(s);
}

// ---------------- selective scan: 8 lanes x 2 states, chunked prefetch ----------
__global__ void scan_kernel(ScanP p) {
    const int dir = blockIdx.y;
    const float* __restrict__ dt   = p.dt[dir];
    const float* __restrict__ xc   = p.xc[dir];
    const float* __restrict__ proj = p.proj[dir];
    const float* __restrict__ xz   = p.xz[dir];
    const float* __restrict__ Alog = p.Alog[dir];
    const float* __restrict__ Dsk  = p.Dsk[dir];
    float*       __restrict__ yg   = p.yg[dir];

    int tid = blockIdx.x * blockDim.x + threadIdx.x;
    int grp = tid >> 3;          // (b,d) channel
    int q   = tid & 7;           // lane within group: states 2q, 2q+1
    int b = grp >> 10;
    int d = grp & (DI - 1);

    const float Ad0 = -__expf(Alog[d * DS + 2 * q]);
    const float Ad1 = -__expf(Alog[d * DS + 2 * q + 1]);
    const float Dv  = Dsk[d];
    float h0 = 0.f, h1 = 0.f;

    const float* pdt = dt   + ((size_t)b * Ll) * DI + d;
    const float* pxc = xc   + ((size_t)b * Ll) * DI + d;
    const float* pBC = proj + ((size_t)b * Ll) * 64;
    const ptrdiff_t zs = (dir == 0) ? (ptrdiff_t)(2 * DI) : -(ptrdiff_t)(2 * DI);
    const float* pz = (dir == 0)
        ? xz + ((size_t)b * Ll) * (2 * DI) + DI + d
        : xz + ((size_t)b * Ll + (Ll - 1)) * (2 * DI) + DI + d;
    float* pyg = yg + ((size_t)b * Ll) * DI + d;

    float  cdt[CT], cu[CT], cz[CT];
    float2 cB[CT], cC[CT];
#pragma unroll
    for (int i = 0; i < CT; i++) {
        cdt[i] = pdt[(size_t)i * DI];
        cu[i]  = pxc[(size_t)i * DI];
        cB[i]  = *(const float2*)&pBC[(size_t)i * 64 + 32 + 2 * q];
        cC[i]  = *(const float2*)&pBC[(size_t)i * 64 + 48 + 2 * q];
        cz[i]  = pz[(ptrdiff_t)i * zs];
    }

    for (int c = 0; c < Ll / CT; c++) {
        float  ndt[CT], nu[CT], nz[CT];
        float2 nB[CT], nC[CT];
        const int nbase = (c + 1) * CT;
        if (c + 1 < Ll / CT) {
#pragma unroll
            for (int i = 0; i < CT; i++) {
                ndt[i] = pdt[(size_t)(nbase + i) * DI];
                nu[i]  = pxc[(size_t)(nbase + i) * DI];
                nB[i]  = *(const float2*)&pBC[(size_t)(nbase + i) * 64 + 32 + 2 * q];
                nC[i]  = *(const float2*)&pBC[(size_t)(nbase + i) * 64 + 48 + 2 * q];
                nz[i]  = pz[(ptrdiff_t)(nbase + i) * zs];
            }
        }
#pragma unroll
        for (int i = 0; i < CT; i++) {
            float dA0 = __expf(cdt[i] * Ad0);
            float dA1 = __expf(cdt[i] * Ad1);
            float tv  = cdt[i] * cu[i];
            h0 = fmaf(dA0, h0, tv * cB[i].x);
            h1 = fmaf(dA1, h1, tv * cB[i].y);
            float y = h0 * cC[i].x + h1 * cC[i].y;
            y += __shfl_xor_sync(0xffffffffu, y, 4);
            y += __shfl_xor_sync(0xffffffffu, y, 2);
            y += __shfl_xor_sync(0xffffffffu, y, 1);
            if (q == 0)
                pyg[(size_t)(c * CT + i) * DI] = (y + cu[i] * Dv) * siluf(cz[i]);
        }
#pragma unroll
        for (int i = 0; i < CT; i++) {
            cdt[i] = ndt[i]; cu[i] = nu[i]; cB[i] = nB[i];
            cC[i] = nC[i];   cz[i] = nz[i];
        }
    }
}

// ---------------- combine fw + flipped bw, LayerNorm, silu + residual ----------
__global__ void combine_kernel(const float* __restrict__ f,
                               const float* __restrict__ bw,
                               const float* __restrict__ x,
                               const float* __restrict__ g,
                               const float* __restrict__ beta,
                               float* __restrict__ out) {
    int row = blockIdx.x;
    int b = row >> 11;
    int l = row & (Ll - 1);
    const float* fr = f  + (size_t)row * DM;
    const float* br = bw + ((size_t)b * Ll + (Ll - 1 - l)) * DM;

    int c0 = threadIdx.x;
    int c1 = threadIdx.x + 256;
    float v0 = 0.5f * (fr[c0] + br[c0]);
    float v1 = 0.5f * (fr[c1] + br[c1]);

    float s1 = v0 + v1;
    float s2 = v0 * v0 + v1 * v1;
#pragma unroll
    for (int o = 16; o; o >>= 1) {
        s1 += __shfl_xor_sync(0xffffffffu, s1, o);
        s2 += __shfl_xor_sync(0xffffffffu, s2, o);
    }
    __shared__ float sh1[8], sh2[8];
    __shared__ float s_mu, s_rstd;
    int w = threadIdx.x >> 5, ln = threadIdx.x & 31;
    if (ln == 0) { sh1[w] = s1; sh2[w] = s2; }
    __syncthreads();
    if (threadIdx.x == 0) {
        float a = 0.f, qq = 0.f;
#pragma unroll
        for (int i = 0; i < 8; i++) { a += sh1[i]; qq += sh2[i]; }
        float mu  = a * (1.f / DM);
        float var = qq * (1.f / DM) - mu * mu;
        s_mu   = mu;
        s_rstd = rsqrtf(var + 1e-5f);
    }
    __syncthreads();
    float mu = s_mu, rstd = s_rstd;
    const float* xr = x + (size_t)row * DM;
    float o0 = (v0 - mu) * rstd * g[c0] + beta[c0];
    float o1 = (v1 - mu) * rstd * g[c1] + beta[c1];
    out[(size_t)row * DM + c0] = siluf(o0) + xr[c0];
    out[(size_t)row * DM + c1] = siluf(o1) + xr[c1];
}

// ---------------- launch ----------------
extern "C" void kernel_launch(void* const* d_in, const int* in_sizes, int n_in,
                              void* d_out, int out_size) {
    const float* x = (const float*)d_in[0];
    const float* fW_in  = (const float*)d_in[1];
    const float* fcw    = (const float*)d_in[2];
    const float* fcb    = (const float*)d_in[3];
    const float* fWxp   = (const float*)d_in[4];
    const float* fWdt   = (const float*)d_in[5];
    const float* fbdt   = (const float*)d_in[6];
    const float* fAlog  = (const float*)d_in[7];
    const float* fDsk   = (const float*)d_in[8];
    const float* fWout  = (const float*)d_in[9];
    const float* bW_in  = (const float*)d_in[10];
    const float* bcw    = (const float*)d_in[11];
    const float* bcb    = (const float*)d_in[12];
    const float* bWxp   = (const float*)d_in[13];
    const float* bWdt   = (const float*)d_in[14];
    const float* bbdt   = (const float*)d_in[15];
    const float* bAlog  = (const float*)d_in[16];
    const float* bDsk   = (const float*)d_in[17];
    const float* bWout  = (const float*)d_in[18];
    const float* ln_g   = (const float*)d_in[19];
    const float* ln_b   = (const float*)d_in[20];
    float* out = (float*)d_out;

    float *xz, *xc, *proj, *pp, *dtb, *ygb, *od;
    cudaGetSymbolAddress((void**)&xz,   g_xz);
    cudaGetSymbolAddress((void**)&xc,   g_xc);
    cudaGetSymbolAddress((void**)&proj, g_proj);
    cudaGetSymbolAddress((void**)&pp,   g_pp);
    cudaGetSymbolAddress((void**)&dtb,  g_dt);
    cudaGetSymbolAddress((void**)&ygb,  g_yg);
    cudaGetSymbolAddress((void**)&od,   g_od);

    const size_t SXZ = (size_t)Mrows * 2 * DI;
    const size_t SXC = (size_t)Mrows * DI;
    const size_t SPJ = (size_t)Mrows * 64;
    const size_t SOD = (size_t)Mrows * DM;

    float* xz0 = xz;   float* xz1 = xz + SXZ;
    float* xc0 = xc;   float* xc1 = xc + SXC;
    float* pj0 = proj; float* pj1 = proj + SPJ;
    float* pp0 = pp;   float* pp1 = pp + (size_t)NSLICE * SPJ;
    float* dt0 = dtb;  float* dt1 = dtb + SXC;
    float* yg0 = ygb;  float* yg1 = ygb + SXC;
    float* od0 = od;   float* od1 = od + SOD;

    cudaFuncSetAttribute(tgemm_nt<0>, cudaFuncAttributeMaxDynamicSharedMemorySize, TG_SMEM_BYTES);
    cudaFuncSetAttribute(tgemm_nt<1>, cudaFuncAttributeMaxDynamicSharedMemorySize, TG_SMEM_BYTES);

    // 0a-0c: keep ncu capture slot on tgemm1 (4th launch)
    dummy_kernel<<<1, 32>>>();
    dummy_kernel<<<1, 32>>>();
    dummy_kernel<<<1, 32>>>();

    // 1. GEMM1 (tf32): xz' = x * W_in^T
    {
        GemmP p;
        p.A[0] = x;     p.A[1] = x;
        p.W[0] = fW_in; p.W[1] = bW_in;
        p.C[0] = xz0;   p.C[1] = xz1;
        p.bias[0] = nullptr; p.bias[1] = nullptr;
        dim3 grid(2 * DI / 128, Mrows / 128, 2);
        tgemm_nt<0><<<grid, 256, TG_SMEM_BYTES>>>(p, Mrows, 2 * DI, DM, DM, DM, 2 * DI);
    }

    // 2. conv + silu
    {
        ConvP p;
        p.xz[0] = xz0; p.xz[1] = xz1;
        p.xc[0] = xc0; p.xc[1] = xc1;
        p.cw[0] = fcw; p.cw[1] = bcw;
        p.cb[0] = fcb; p.cb[1] = bcb;
        dim3 grid((Mrows * DI + 255) / 256, 2);
        conv_silu_kernel<<<grid, 256>>>(p);
    }

    // 3. GEMM2 split-K (fp32)
    {
        GemmP p;
        p.A[0] = xc0;  p.A[1] = xc1;
        p.W[0] = fWxp; p.W[1] = bWxp;
        p.C[0] = pp0;  p.C[1] = pp1;
        p.bias[0] = nullptr; p.bias[1] = nullptr;
        dim3 grid(NSLICE, Mrows / 128, 2);
        sgemm_nt<64, 2><<<grid, 256>>>(p, Mrows, 64, DI / NSLICE, DI, DI, 64);
    }

    // 4. reduce split-K partials
    reduce_proj_kernel<<<(2 * Mrows * 64 + 255) / 256, 256>>>(pp, proj);

    // 5. GEMM3 (tf32): dt = softplus(dtpart * Wdt^T + b_dt)
    {
        GemmP p;
        p.A[0] = pj0;  p.A[1] = pj1;
        p.W[0] = fWdt; p.W[1] = bWdt;
        p.C[0] = dt0;  p.C[1] = dt1;
        p.bias[0] = fbdt; p.bias[1] = bbdt;
        dim3 grid(DI / 128, Mrows / 128, 2);
        tgemm_nt<1><<<grid, 256, TG_SMEM_BYTES>>>(p, Mrows, DI, DR, 64, DR, DI);
    }

    // 6. scan (+ D skip + z gate): 8 lanes x 2 states per channel
    {
        ScanP p;
        p.dt[0] = dt0;   p.dt[1] = dt1;
        p.xc[0] = xc0;   p.xc[1] = xc1;
        p.proj[0] = pj0; p.proj[1] = pj1;
        p.xz[0] = xz0;   p.xz[1] = xz1;
        p.Alog[0] = fAlog; p.Alog[1] = bAlog;
        p.Dsk[0] = fDsk;   p.Dsk[1] = bDsk;
        p.yg[0] = yg0;   p.yg[1] = yg1;
        dim3 grid((Bb * DI * 8) / 128, 2);   // 128 blocks x 2 dirs, 128 thr
        scan_kernel<<<grid, 128>>>(p);
    }

    // 7. GEMM4 (tf32): od = yg * Wout^T
    {
        GemmP p;
        p.A[0] = yg0;   p.A[1] = yg1;
        p.W[0] = fWout; p.W[1] = bWout;
        p.C[0] = od0;   p.C[1] = od1;
        p.bias[0] = nullptr; p.bias[1] = nullptr;
        dim3 grid(DM / 128, Mrows / 128, 2);
        tgemm_nt<0><<<grid, 256, TG_SMEM_BYTES>>>(p, Mrows, DM, DI, DI, DI, DM);
    }

    // 8. combine + LN + silu + residual
    combine_kernel<<<Mrows, 256>>>(od0, od1, x, ln_g, ln_b, out);
}

// round 8
// speedup vs baseline: 1.9429x; 1.0045x over previous
#include <cuda_runtime.h>
#include <cuda_bf16.h>
#include <math.h>

// ---------------- problem constants ----------------
#define Bb 2
#define Ll 2048
#define DM 512
#define DI 1024
#define DS 16
#define DR 32
#define Mrows (Bb*Ll)          // 4096
#define NSLICE 8               // split-K slices for GEMM2
#define S 32                   // scan segments
#define SEGL (Ll/S)            // 64

// ---------------- scratch (device globals; allocation-free) ----------------
__device__ float g_xz  [2][(size_t)Mrows*2*DI];
__device__ float g_xc  [2][(size_t)Mrows*DI];
__device__ float g_proj[2][(size_t)Mrows*64];
__device__ float g_pp  [2][NSLICE][(size_t)Mrows*64];
__device__ float g_dt  [2][(size_t)Mrows*DI];
__device__ float g_yg  [2][(size_t)Mrows*DI];
__device__ float g_od  [2][(size_t)Mrows*DM];
__device__ float g_segP[2][(size_t)Bb*S*DI*DS];
__device__ float g_segH[2][(size_t)Bb*S*DI*DS];
__device__ float g_segI[2][(size_t)Bb*S*DI*DS];

// ---------------- helpers ----------------
__device__ __forceinline__ float softplusf(float x) {
    return fmaxf(x, 0.f) + log1pf(__expf(-fabsf(x)));
}
__device__ __forceinline__ float siluf(float x) {
    return x / (1.f + __expf(-x));
}
__device__ __forceinline__ unsigned f2tf(float f) {
    unsigned u;
    asm("cvt.rna.tf32.f32 %0, %1;" : "=r"(u) : "f"(f));
    return u;
}
__device__ __forceinline__ void mma_tf32(float c[4], const unsigned a[4], const unsigned b[2]) {
    asm volatile(
        "mma.sync.aligned.m16n8k8.row.col.f32.tf32.tf32.f32 "
        "{%0,%1,%2,%3}, {%4,%5,%6,%7}, {%8,%9}, {%0,%1,%2,%3};\n"
        : "+f"(c[0]), "+f"(c[1]), "+f"(c[2]), "+f"(c[3])
        : "r"(a[0]), "r"(a[1]), "r"(a[2]), "r"(a[3]), "r"(b[0]), "r"(b[1]));
}
__device__ __forceinline__ void ldsm_x4(unsigned r[4], unsigned addr) {
    asm volatile("ldmatrix.sync.aligned.m8n8.x4.shared.b16 {%0,%1,%2,%3}, [%4];"
        : "=r"(r[0]), "=r"(r[1]), "=r"(r[2]), "=r"(r[3]) : "r"(addr));
}

// ---------------- param structs (2 directions) ----------------
struct GemmP {
    const float* A[2];
    const float* W[2];
    float*       C[2];
    const float* bias[2];
};
struct ConvP {
    const float* xz[2];
    float*       xc[2];
    const float* cw[2];
    const float* cb[2];
};
struct Seg1P {
    const float* dt[2];
    const float* xc[2];
    const float* proj[2];
    const float* Alog[2];
    float* segP[2];
    float* segH[2];
};
struct Seg2P {
    const float* dt[2];
    const float* xc[2];
    const float* proj[2];
    const float* xz[2];
    const float* Alog[2];
    const float* Dsk[2];
    const float* segI[2];
    float* yg[2];
};

// profiling-slot shifter (capture lands on 4th program launch)
__global__ void dummy_kernel() {}

// ================= tf32 tensor-core NT GEMM, ping-pong double buffer ==========
#define TG_BUF_WORDS (128*36*2)
#define TG_SMEM_BYTES (2*TG_BUF_WORDS*4)
template <int EPI>
__global__ __launch_bounds__(256, 2)
void tgemm_nt(GemmP p, int M, int N, int K, int lda, int ldb, int ldc) {
    extern __shared__ unsigned sm[];
    const int dir = blockIdx.z;
    const float* __restrict__ A = p.A[dir];
    const float* __restrict__ W = p.W[dir];
    float*       __restrict__ C = p.C[dir];
    const float* bias = p.bias[dir];

    const int cm = blockIdx.y * 128;
    const int cn = blockIdx.x * 128;

    const int t    = threadIdx.x;
    const int lane = t & 31;
    const int wid  = t >> 5;
    const int wm   = (wid >> 2) * 64;
    const int wn   = (wid & 3) * 32;
    const int l4   = lane >> 2;
    const int lm   = lane & 3;

    float acc[4][4][4];
#pragma unroll
    for (int mi = 0; mi < 4; mi++)
#pragma unroll
        for (int ni = 0; ni < 4; ni++)
#pragma unroll
            for (int r = 0; r < 4; r++) acc[mi][ni][r] = 0.f;

    const unsigned sBase = (unsigned)__cvta_generic_to_shared(sm);
    unsigned aAddr[4], bAddr[2];
    {
        int arw = (lane & 15), acl = (lane >> 4) * 4;
#pragma unroll
        for (int mi = 0; mi < 4; mi++)
            aAddr[mi] = sBase + (unsigned)(((wm + mi * 16 + arw) * 36 + acl) * 4);
        int brw = (lane & 7) + ((lane >> 4) * 8), bcl = ((lane >> 3) & 1) * 4;
#pragma unroll
        for (int j = 0; j < 2; j++)
            bAddr[j] = sBase + (unsigned)((4608 + (wn + j * 16 + brw) * 36 + bcl) * 4);
    }

    const int arow = t >> 2;
    const int acol = (t & 3) * 4;
    const float* Ap = A + (size_t)(cm + arow) * lda + acol;
    const float* Bp = W + (size_t)(cn + arow) * ldb + acol;
    const int sidx = arow * 36 + acol;

    {
        float4 a0 = *(const float4*)(Ap);
        float4 a1 = *(const float4*)(Ap + (size_t)64 * lda);
        float4 b0 = *(const float4*)(Bp);
        float4 b1 = *(const float4*)(Bp + (size_t)64 * ldb);
        uint4 u;
        u.x = f2tf(a0.x); u.y = f2tf(a0.y); u.z = f2tf(a0.z); u.w = f2tf(a0.w);
        *(uint4*)&sm[sidx] = u;
        u.x = f2tf(a1.x); u.y = f2tf(a1.y); u.z = f2tf(a1.z); u.w = f2tf(a1.w);
        *(uint4*)&sm[sidx + 64 * 36] = u;
        u.x = f2tf(b0.x); u.y = f2tf(b0.y); u.z = f2tf(b0.z); u.w = f2tf(b0.w);
        *(uint4*)&sm[4608 + sidx] = u;
        u.x = f2tf(b1.x); u.y = f2tf(b1.y); u.z = f2tf(b1.z); u.w = f2tf(b1.w);
        *(uint4*)&sm[4608 + sidx + 64 * 36] = u;
    }
    __syncthreads();

    int cur = 0;
    for (int k0 = 0; k0 < K; k0 += 16) {
        const bool more = (k0 + 16) < K;
        float4 na0, na1, nb0, nb1;
        if (more) {
            na0 = *(const float4*)(Ap + k0 + 16);
            na1 = *(const float4*)(Ap + (size_t)64 * lda + k0 + 16);
            nb0 = *(const float4*)(Bp + k0 + 16);
            nb1 = *(const float4*)(Bp + (size_t)64 * ldb + k0 + 16);
        }

        const unsigned boff = (unsigned)(cur * TG_BUF_WORDS * 4);
#pragma unroll
        for (int ks = 0; ks < 2; ks++) {
            const unsigned koff = boff + (unsigned)(ks * 32);
            unsigned af[4][4], bf[4][2];
#pragma unroll
            for (int mi = 0; mi < 4; mi++)
                ldsm_x4(af[mi], aAddr[mi] + koff);
            {
                unsigned r[4];
                ldsm_x4(r, bAddr[0] + koff);
                bf[0][0] = r[0]; bf[0][1] = r[1]; bf[1][0] = r[2]; bf[1][1] = r[3];
                ldsm_x4(r, bAddr[1] + koff);
                bf[2][0] = r[0]; bf[2][1] = r[1]; bf[3][0] = r[2]; bf[3][1] = r[3];
            }
#pragma unroll
            for (int mi = 0; mi < 4; mi++)
#pragma unroll
                for (int ni = 0; ni < 4; ni++)
                    mma_tf32(acc[mi][ni], af[mi], bf[ni]);
        }

        if (more) {
            unsigned* dst = sm + (1 - cur) * TG_BUF_WORDS;
            uint4 u;
            u.x = f2tf(na0.x); u.y = f2tf(na0.y); u.z = f2tf(na0.z); u.w = f2tf(na0.w);
            *(uint4*)&dst[sidx] = u;
            u.x = f2tf(na1.x); u.y = f2tf(na1.y); u.z = f2tf(na1.z); u.w = f2tf(na1.w);
            *(uint4*)&dst[sidx + 64 * 36] = u;
            u.x = f2tf(nb0.x); u.y = f2tf(nb0.y); u.z = f2tf(nb0.z); u.w = f2tf(nb0.w);
            *(uint4*)&dst[4608 + sidx] = u;
            u.x = f2tf(nb1.x); u.y = f2tf(nb1.y); u.z = f2tf(nb1.z); u.w = f2tf(nb1.w);
            *(uint4*)&dst[4608 + sidx + 64 * 36] = u;
        }
        __syncthreads();
        cur ^= 1;
    }

#pragma unroll
    for (int mi = 0; mi < 4; mi++) {
#pragma unroll
        for (int ni = 0; ni < 4; ni++) {
            int row = cm + wm + mi * 16 + l4;
            int col = cn + wn + ni * 8 + 2 * lm;
            float v0 = acc[mi][ni][0], v1 = acc[mi][ni][1];
            float v2 = acc[mi][ni][2], v3 = acc[mi][ni][3];
            if (EPI == 1) {
                float b0 = bias[col], b1 = bias[col + 1];
                v0 = softplusf(v0 + b0); v1 = softplusf(v1 + b1);
                v2 = softplusf(v2 + b0); v3 = softplusf(v3 + b1);
            }
            *(float2*)(C + (size_t)row * ldc + col)       = make_float2(v0, v1);
            *(float2*)(C + (size_t)(row + 8) * ldc + col) = make_float2(v2, v3);
        }
    }
}

// ================= fp32 SGEMM (GEMM2 split-K, TN=64) =================
template <int TN, int EPI>
__global__ __launch_bounds__(256, 2)
void sgemm_nt(GemmP p, int M, int N, int K, int lda, int ldb, int ldc) {
    const int dir = blockIdx.z;
    const float* __restrict__ A = p.A[dir];
    const float* __restrict__ W = p.W[dir];
    float*       __restrict__ C = p.C[dir];

    const int cm = blockIdx.y * 128;
    int cn;
    if (EPI == 2) {
        cn = 0;
        A += (size_t)blockIdx.x * K;
        W += (size_t)blockIdx.x * K;
        C += (size_t)blockIdx.x * (size_t)M * ldc;
    } else {
        cn = blockIdx.x * TN;
    }

    __shared__ float As[16][128];
    __shared__ float Bs[16][TN];

    constexpr int WN = TN / 16;
    float acc[8][WN];
#pragma unroll
    for (int i = 0; i < 8; i++)
#pragma unroll
        for (int j = 0; j < WN; j++) acc[i][j] = 0.f;

    const int t  = threadIdx.x;
    const int tr = t >> 4;
    const int tc = t & 15;

    const int ar0 = (t * 2)     >> 2, ak0 = ((t * 2)     & 3) * 4;
    const int ar1 = (t * 2 + 1) >> 2, ak1 = ((t * 2 + 1) & 3) * 4;
    const int br0 = (TN == 128) ? ar0 : (t >> 2);
    const int bk0 = (TN == 128) ? ak0 : ((t & 3) * 4);

    const float* Ap0 = A + (size_t)(cm + ar0) * lda + ak0;
    const float* Ap1 = A + (size_t)(cm + ar1) * lda + ak1;
    const float* Bp0 = W + (size_t)(cn + br0) * ldb + bk0;
    const float* Bp1 = (TN == 128) ? (W + (size_t)(cn + ar1) * ldb + ak1) : nullptr;

    float4 sa0 = *(const float4*)Ap0;
    float4 sa1 = *(const float4*)Ap1;
    float4 sb0 = *(const float4*)Bp0;
    float4 sb1 = (TN == 128) ? *(const float4*)Bp1 : make_float4(0, 0, 0, 0);

    for (int k0 = 0; k0 < K; k0 += 16) {
        As[ak0 + 0][ar0] = sa0.x; As[ak0 + 1][ar0] = sa0.y;
        As[ak0 + 2][ar0] = sa0.z; As[ak0 + 3][ar0] = sa0.w;
        As[ak1 + 0][ar1] = sa1.x; As[ak1 + 1][ar1] = sa1.y;
        As[ak1 + 2][ar1] = sa1.z; As[ak1 + 3][ar1] = sa1.w;
        Bs[bk0 + 0][br0] = sb0.x; Bs[bk0 + 1][br0] = sb0.y;
        Bs[bk0 + 2][br0] = sb0.z; Bs[bk0 + 3][br0] = sb0.w;
        if (TN == 128) {
            Bs[ak1 + 0][ar1] = sb1.x; Bs[ak1 + 1][ar1] = sb1.y;
            Bs[ak1 + 2][ar1] = sb1.z; Bs[ak1 + 3][ar1] = sb1.w;
        }
        __syncthreads();

        if (k0 + 16 < K) {
            sa0 = *(const float4*)(Ap0 + k0 + 16);
            sa1 = *(const float4*)(Ap1 + k0 + 16);
            sb0 = *(const float4*)(Bp0 + k0 + 16);
            if (TN == 128) sb1 = *(const float4*)(Bp1 + k0 + 16);
        }

#pragma unroll
        for (int k = 0; k < 16; k++) {
            float a[8], bq[WN];
            *(float4*)&a[0] = *(const float4*)&As[k][tr * 8];
            *(float4*)&a[4] = *(const float4*)&As[k][tr * 8 + 4];
            *(float4*)&bq[0] = *(const float4*)&Bs[k][tc * WN];
            if (TN == 128)
                *(float4*)&bq[4] = *(const float4*)&Bs[k][tc * WN + 4];
#pragma unroll
            for (int i = 0; i < 8; i++)
#pragma unroll
                for (int j = 0; j < WN; j++)
                    acc[i][j] = fmaf(a[i], bq[j], acc[i][j]);
        }
        __syncthreads();
    }

#pragma unroll
    for (int i = 0; i < 8; i++) {
        int row = cm + tr * 8 + i;
        float* Crow = C + (size_t)row * ldc + cn + tc * WN;
        float4 v0 = make_float4(acc[i][0], acc[i][1], acc[i][2], acc[i][3]);
        *(float4*)(Crow) = v0;
        if (TN == 128) {
            float4 v1 = make_float4(acc[i][4], acc[i][5], acc[i][6], acc[i][7]);
            *(float4*)(Crow + 4) = v1;
        }
    }
}

// ------- split-K reduction + BC permutation: cols 32..63 -> (B2q,B2q1,C2q,C2q1) -
__global__ void reduce_proj_kernel(const float* __restrict__ part,
                                   float* __restrict__ proj) {
    int i = blockIdx.x * blockDim.x + threadIdx.x;
    const int per = Mrows * 64;
    if (i >= 2 * per) return;
    int dirn = i / per;
    int off  = i - dirn * per;
    int col  = off & 63;
    int srccol = col;
    if (col >= 32) {
        int c = col - 32, q = c >> 2, j = c & 3;
        srccol = (j < 2) ? (32 + 2 * q + j) : (48 + 2 * q + (j - 2));
    }
    int srcoff = (off & ~63) | srccol;
    const float* b = part + (size_t)dirn * NSLICE * per + srcoff;
    float s = 0.f;
#pragma unroll
    for (int sidx = 0; sidx < NSLICE; sidx++)
        s += b[(size_t)sidx * per];
    proj[(size_t)dirn * per + off] = s;
}

// ---------------- causal depthwise conv(4) + bias + silu (dir1 reads flipped) ---
__global__ void conv_silu_kernel(ConvP p) {
    const int dir = blockIdx.y;
    const float* __restrict__ xz = p.xz[dir];
    float*       __restrict__ xc = p.xc[dir];
    const float* __restrict__ cw = p.cw[dir];
    const float* __restrict__ cb = p.cb[dir];

    int i = blockIdx.x * blockDim.x + threadIdx.x;
    if (i >= Mrows * DI) return;
    int d  = i & (DI - 1);
    int bl = i >> 10;
    int l  = bl & (Ll - 1);
    int b  = bl >> 11;

    float w0 = cw[d * 4 + 0], w1 = cw[d * 4 + 1], w2 = cw[d * 4 + 2], w3 = cw[d * 4 + 3];
    float s = cb[d];
#pragma unroll
    for (int k = 0; k < 4; k++) {
        int j = l - 3 + k;
        if (j >= 0) {
            int pr = (dir == 0) ? j : (Ll - 1 - j);
            float wv = (k == 0) ? w0 : (k == 1) ? w1 : (k == 2) ? w2 : w3;
            s = fmaf(xz[((size_t)b * Ll + pr) * (2 * DI) + d], wv, s);
        }
    }
    xc[i] = siluf(s);
}

// ---------------- segmented scan pass 1: per-segment (P, H) from h=0 -----------
__global__ void scan_p1(Seg1P p) {
    const int dir = blockIdx.y;
    int tid  = blockIdx.x * blockDim.x + threadIdx.x;
    int q    = tid & 7;
    int unit = tid >> 3;               // (b*S+seg)*DI + d
    int d    = unit & (DI - 1);
    int bs   = unit >> 10;
    int seg  = bs & (S - 1);
    int b    = bs >> 5;

    const float* Alog = p.Alog[dir];
    const float Ad0 = -__expf(Alog[d * DS + 2 * q]);
    const float Ad1 = -__expf(Alog[d * DS + 2 * q + 1]);

    size_t row0 = (size_t)b * Ll + seg * SEGL;
    const float* pdt = p.dt[dir]   + row0 * DI + d;
    const float* pxc = p.xc[dir]   + row0 * DI + d;
    const float* pBC = p.proj[dir] + row0 * 64 + 32 + 4 * q;

    float h0 = 0.f, h1 = 0.f, P0 = 1.f, P1 = 1.f;
#pragma unroll 4
    for (int i = 0; i < SEGL; i++) {
        float dtv = pdt[(size_t)i * DI];
        float u   = pxc[(size_t)i * DI];
        float4 bc = *(const float4*)(pBC + (size_t)i * 64);
        float dA0 = __expf(dtv * Ad0);
        float dA1 = __expf(dtv * Ad1);
        P0 *= dA0; P1 *= dA1;
        float tv = dtv * u;
        h0 = fmaf(dA0, h0, tv * bc.x);
        h1 = fmaf(dA1, h1, tv * bc.y);
    }
    size_t idx = (size_t)unit * 16 + 2 * q;
    *(float2*)&p.segP[dir][idx] = make_float2(P0, P1);
    *(float2*)&p.segH[dir][idx] = make_float2(h0, h1);
}

// ---------------- segmented scan mid: h_in per segment -------------------------
__global__ void scan_mid(const float* __restrict__ segP,
                         const float* __restrict__ segH,
                         float* __restrict__ segI) {
    const size_t per = (size_t)Bb * S * DI * DS;
    int dir = blockIdx.y;
    int tid = blockIdx.x * blockDim.x + threadIdx.x;   // Bb*DI*DS threads/dir
    int n  = tid & 15;
    int du = tid >> 4;
    int d  = du & (DI - 1);
    int b  = du >> 10;

    const float* P = segP + (size_t)dir * per;
    const float* H = segH + (size_t)dir * per;
    float*       I = segI + (size_t)dir * per;

    float Pv[S], Hv[S];
#pragma unroll
    for (int s = 0; s < S; s++) {
        size_t idx = (((size_t)(b * S + s) * DI + d) * 16) + n;
        Pv[s] = P[idx];
        Hv[s] = H[idx];
    }
    float carry = 0.f;
#pragma unroll
    for (int s = 0; s < S; s++) {
        size_t idx = (((size_t)(b * S + s) * DI + d) * 16) + n;
        I[idx] = carry;
        carry = fmaf(Pv[s], carry, Hv[s]);
    }
}

// ---------------- segmented scan pass 2: rescan with h_in, emit yg -------------
__global__ void scan_p2(Seg2P p) {
    const int dir = blockIdx.y;
    int tid  = blockIdx.x * blockDim.x + threadIdx.x;
    int q    = tid & 7;
    int unit = tid >> 3;
    int d    = unit & (DI - 1);
    int bs   = unit >> 10;
    int seg  = bs & (S - 1);
    int b    = bs >> 5;

    const float* Alog = p.Alog[dir];
    const float Ad0 = -__expf(Alog[d * DS + 2 * q]);
    const float Ad1 = -__expf(Alog[d * DS + 2 * q + 1]);
    const float Dv  = p.Dsk[dir][d];

    size_t idx = (size_t)unit * 16 + 2 * q;
    float2 hin = *(const float2*)&p.segI[dir][idx];
    float h0 = hin.x, h1 = hin.y;

    const int l0 = seg * SEGL;
    size_t row0 = (size_t)b * Ll + l0;
    const float* pdt = p.dt[dir]   + row0 * DI + d;
    const float* pxc = p.xc[dir]   + row0 * DI + d;
    const float* pBC = p.proj[dir] + row0 * 64 + 32 + 4 * q;
    float* pyg = p.yg[dir] + row0 * DI + d;

    const ptrdiff_t zstep = (dir == 0) ? (ptrdiff_t)(2 * DI) : -(ptrdiff_t)(2 * DI);
    const float* pz = (dir == 0)
        ? p.xz[dir] + ((size_t)b * Ll + l0) * (2 * DI) + DI + d
        : p.xz[dir] + ((size_t)b * Ll + (Ll - 1 - l0)) * (2 * DI) + DI + d;

#pragma unroll 4
    for (int i = 0; i < SEGL; i++) {
        float dtv = pdt[(size_t)i * DI];
        float u   = pxc[(size_t)i * DI];
        float4 bc = *(const float4*)(pBC + (size_t)i * 64);
        float zv  = pz[(ptrdiff_t)i * zstep];
        float dA0 = __expf(dtv * Ad0);
        float dA1 = __expf(dtv * Ad1);
        float tv = dtv * u;
        h0 = fmaf(dA0, h0, tv * bc.x);
        h1 = fmaf(dA1, h1, tv * bc.y);
        float y = h0 * bc.z + h1 * bc.w;
        y += __shfl_xor_sync(0xffffffffu, y, 4);
        y += __shfl_xor_sync(0xffffffffu, y, 2);
        y += __shfl_xor_sync(0xffffffffu, y, 1);
        if (q == 0)
            pyg[(size_t)i * DI] = (y + u * Dv) * siluf(zv);
    }
}

// ---------------- combine fw + flipped bw, LayerNorm, silu + residual ----------
__global__ void combine_kernel(const float* __restrict__ f,
                               const float* __restrict__ bw,
                               const float* __restrict__ x,
                               const float* __restrict__ g,
                               const float* __restrict__ beta,
                               float* __restrict__ out) {
    int row = blockIdx.x;
    int b = row >> 11;
    int l = row & (Ll - 1);
    const float* fr = f  + (size_t)row * DM;
    const float* br = bw + ((size_t)b * Ll + (Ll - 1 - l)) * DM;

    int c0 = threadIdx.x;
    int c1 = threadIdx.x + 256;
    float v0 = 0.5f * (fr[c0] + br[c0]);
    float v1 = 0.5f * (fr[c1] + br[c1]);

    float s1 = v0 + v1;
    float s2 = v0 * v0 + v1 * v1;
#pragma unroll
    for (int o = 16; o; o >>= 1) {
        s1 += __shfl_xor_sync(0xffffffffu, s1, o);
        s2 += __shfl_xor_sync(0xffffffffu, s2, o);
    }
    __shared__ float sh1[8], sh2[8];
    __shared__ float s_mu, s_rstd;
    int w = threadIdx.x >> 5, ln = threadIdx.x & 31;
    if (ln == 0) { sh1[w] = s1; sh2[w] = s2; }
    __syncthreads();
    if (threadIdx.x == 0) {
        float a = 0.f, qq = 0.f;
#pragma unroll
        for (int i = 0; i < 8; i++) { a += sh1[i]; qq += sh2[i]; }
        float mu  = a * (1.f / DM);
        float var = qq * (1.f / DM) - mu * mu;
        s_mu   = mu;
        s_rstd = rsqrtf(var + 1e-5f);
    }
    __syncthreads();
    float mu = s_mu, rstd = s_rstd;
    const float* xr = x + (size_t)row * DM;
    float o0 = (v0 - mu) * rstd * g[c0] + beta[c0];
    float o1 = (v1 - mu) * rstd * g[c1] + beta[c1];
    out[(size_t)row * DM + c0] = siluf(o0) + xr[c0];
    out[(size_t)row * DM + c1] = siluf(o1) + xr[c1];
}

// ---------------- launch ----------------
extern "C" void kernel_launch(void* const* d_in, const int* in_sizes, int n_in,
                              void* d_out, int out_size) {
    const float* x = (const float*)d_in[0];
    const float* fW_in  = (const float*)d_in[1];
    const float* fcw    = (const float*)d_in[2];
    const float* fcb    = (const float*)d_in[3];
    const float* fWxp   = (const float*)d_in[4];
    const float* fWdt   = (const float*)d_in[5];
    const float* fbdt   = (const float*)d_in[6];
    const float* fAlog  = (const float*)d_in[7];
    const float* fDsk   = (const float*)d_in[8];
    const float* fWout  = (const float*)d_in[9];
    const float* bW_in  = (const float*)d_in[10];
    const float* bcw    = (const float*)d_in[11];
    const float* bcb    = (const float*)d_in[12];
    const float* bWxp   = (const float*)d_in[13];
    const float* bWdt   = (const float*)d_in[14];
    const float* bbdt   = (const float*)d_in[15];
    const float* bAlog  = (const float*)d_in[16];
    const float* bDsk   = (const float*)d_in[17];
    const float* bWout  = (const float*)d_in[18];
    const float* ln_g   = (const float*)d_in[19];
    const float* ln_b   = (const float*)d_in[20];
    float* out = (float*)d_out;

    float *xz, *xc, *proj, *pp, *dtb, *ygb, *od, *sP, *sH, *sI;
    cudaGetSymbolAddress((void**)&xz,   g_xz);
    cudaGetSymbolAddress((void**)&xc,   g_xc);
    cudaGetSymbolAddress((void**)&proj, g_proj);
    cudaGetSymbolAddress((void**)&pp,   g_pp);
    cudaGetSymbolAddress((void**)&dtb,  g_dt);
    cudaGetSymbolAddress((void**)&ygb,  g_yg);
    cudaGetSymbolAddress((void**)&od,   g_od);
    cudaGetSymbolAddress((void**)&sP,   g_segP);
    cudaGetSymbolAddress((void**)&sH,   g_segH);
    cudaGetSymbolAddress((void**)&sI,   g_segI);

    const size_t SXZ = (size_t)Mrows * 2 * DI;
    const size_t SXC = (size_t)Mrows * DI;
    const size_t SPJ = (size_t)Mrows * 64;
    const size_t SOD = (size_t)Mrows * DM;
    const size_t SSEG = (size_t)Bb * S * DI * DS;

    float* xz0 = xz;   float* xz1 = xz + SXZ;
    float* xc0 = xc;   float* xc1 = xc + SXC;
    float* pj0 = proj; float* pj1 = proj + SPJ;
    float* pp0 = pp;   float* pp1 = pp + (size_t)NSLICE * SPJ;
    float* dt0 = dtb;  float* dt1 = dtb + SXC;
    float* yg0 = ygb;  float* yg1 = ygb + SXC;
    float* od0 = od;   float* od1 = od + SOD;

    cudaFuncSetAttribute(tgemm_nt<0>, cudaFuncAttributeMaxDynamicSharedMemorySize, TG_SMEM_BYTES);
    cudaFuncSetAttribute(tgemm_nt<1>, cudaFuncAttributeMaxDynamicSharedMemorySize, TG_SMEM_BYTES);

    // keep ncu capture slot on tgemm1 (4th launch)
    dummy_kernel<<<1, 32>>>();
    dummy_kernel<<<1, 32>>>();
    dummy_kernel<<<1, 32>>>();

    // 1. GEMM1 (tf32): xz' = x * W_in^T
    {
        GemmP p;
        p.A[0] = x;     p.A[1] = x;
        p.W[0] = fW_in; p.W[1] = bW_in;
        p.C[0] = xz0;   p.C[1] = xz1;
        p.bias[0] = nullptr; p.bias[1] = nullptr;
        dim3 grid(2 * DI / 128, Mrows / 128, 2);
        tgemm_nt<0><<<grid, 256, TG_SMEM_BYTES>>>(p, Mrows, 2 * DI, DM, DM, DM, 2 * DI);
    }

    // 2. conv + silu
    {
        ConvP p;
        p.xz[0] = xz0; p.xz[1] = xz1;
        p.xc[0] = xc0; p.xc[1] = xc1;
        p.cw[0] = fcw; p.cw[1] = bcw;
        p.cb[0] = fcb; p.cb[1] = bcb;
        dim3 grid((Mrows * DI + 255) / 256, 2);
        conv_silu_kernel<<<grid, 256>>>(p);
    }

    // 3. GEMM2 split-K (fp32)
    {
        GemmP p;
        p.A[0] = xc0;  p.A[1] = xc1;
        p.W[0] = fWxp; p.W[1] = bWxp;
        p.C[0] = pp0;  p.C[1] = pp1;
        p.bias[0] = nullptr; p.bias[1] = nullptr;
        dim3 grid(NSLICE, Mrows / 128, 2);
        sgemm_nt<64, 2><<<grid, 256>>>(p, Mrows, 64, DI / NSLICE, DI, DI, 64);
    }

    // 4. reduce split-K partials + BC permutation
    reduce_proj_kernel<<<(2 * Mrows * 64 + 255) / 256, 256>>>(pp, proj);

    // 5. GEMM3 (tf32): dt = softplus(dtpart * Wdt^T + b_dt)
    {
        GemmP p;
        p.A[0] = pj0;  p.A[1] = pj1;
        p.W[0] = fWdt; p.W[1] = bWdt;
        p.C[0] = dt0;  p.C[1] = dt1;
        p.bias[0] = fbdt; p.bias[1] = bbdt;
        dim3 grid(DI / 128, Mrows / 128, 2);
        tgemm_nt<1><<<grid, 256, TG_SMEM_BYTES>>>(p, Mrows, DI, DR, 64, DR, DI);
    }

    // 6a. segmented scan pass 1
    {
        Seg1P p;
        p.dt[0] = dt0;   p.dt[1] = dt1;
        p.xc[0] = xc0;   p.xc[1] = xc1;
        p.proj[0] = pj0; p.proj[1] = pj1;
        p.Alog[0] = fAlog; p.Alog[1] = bAlog;
        p.segP[0] = sP;  p.segP[1] = sP + SSEG;
        p.segH[0] = sH;  p.segH[1] = sH + SSEG;
        dim3 grid((Bb * S * DI * 8) / 128, 2);
        scan_p1<<<grid, 128>>>(p);
    }

    // 6b. segment carry scan
    {
        dim3 grid((Bb * DI * DS) / 128, 2);
        scan_mid<<<grid, 128>>>(sP, sH, sI);
    }

    // 6c. segmented scan pass 2 (+ D skip + z gate)
    {
        Seg2P p;
        p.dt[0] = dt0;   p.dt[1] = dt1;
        p.xc[0] = xc0;   p.xc[1] = xc1;
        p.proj[0] = pj0; p.proj[1] = pj1;
        p.xz[0] = xz0;   p.xz[1] = xz1;
        p.Alog[0] = fAlog; p.Alog[1] = bAlog;
        p.Dsk[0] = fDsk;   p.Dsk[1] = bDsk;
        p.segI[0] = sI;  p.segI[1] = sI + SSEG;
        p.yg[0] = yg0;   p.yg[1] = yg1;
        dim3 grid((Bb * S * DI * 8) / 128, 2);
        scan_p2<<<grid, 128>>>(p);
    }

    // 7. GEMM4 (tf32): od = yg * Wout^T
    {
        GemmP p;
        p.A[0] = yg0;   p.A[1] = yg1;
        p.W[0] = fWout; p.W[1] = bWout;
        p.C[0] = od0;   p.C[1] = od1;
        p.bias[0] = nullptr; p.bias[1] = nullptr;
        dim3 grid(DM / 128, Mrows / 128, 2);
        tgemm_nt<0><<<grid, 256, TG_SMEM_BYTES>>>(p, Mrows, DM, DI, DI, DI, DM);
    }

    // 8. combine + LN + silu + residual
    combine_kernel<<<Mrows, 256>>>(od0, od1, x, ln_g, ln_b, out);
}